// round 1
// baseline (speedup 1.0000x reference)
#include <cuda_runtime.h>
#include <cuda_bf16.h>
#include <math.h>

#define S_LEN 2048
#define D_DIM 1024
#define H_NUM 16
#define HD_DIM 64
#define FF_DIM 4096
#define DEPTH 2
#define NSEG 4
#define EPS 1e-6f

// ---------------- scratch (device globals; allocation-free) ----------------
__device__ float g_h  [S_LEN * D_DIM];        // LN output
__device__ float g_qkv[S_LEN * 3 * D_DIM];    // qkv projection
__device__ float g_ao [S_LEN * D_DIM];        // attention output
__device__ float g_ff [S_LEN * FF_DIM];       // fc1 output

// ---------------- LayerNorm: one block per row ----------------
__global__ void ln_kernel(const float* __restrict__ x,
                          const float* __restrict__ g,
                          const float* __restrict__ b,
                          float* __restrict__ out) {
    const int row = blockIdx.x;
    const int tid = threadIdx.x;                // 256 threads
    const float* xr = x + (size_t)row * D_DIM;
    __shared__ float red[256];

    float s = 0.f;
    for (int i = tid; i < D_DIM; i += 256) s += xr[i];
    red[tid] = s; __syncthreads();
    for (int o = 128; o > 0; o >>= 1) { if (tid < o) red[tid] += red[tid + o]; __syncthreads(); }
    const float mean = red[0] * (1.f / D_DIM);
    __syncthreads();

    float v = 0.f;
    for (int i = tid; i < D_DIM; i += 256) { float d = xr[i] - mean; v += d * d; }
    red[tid] = v; __syncthreads();
    for (int o = 128; o > 0; o >>= 1) { if (tid < o) red[tid] += red[tid + o]; __syncthreads(); }
    const float rstd = rsqrtf(red[0] * (1.f / D_DIM) + EPS);

    for (int i = tid; i < D_DIM; i += 256)
        out[(size_t)row * D_DIM + i] = (xr[i] - mean) * rstd * g[i] + b[i];
}

// ---------------- SGEMM 128x128x8, 256 threads, 8x8 per thread ----------------
// C[M,N] = A[M,K] @ B[K,N] + bias  (+ epilogue)
// EPI: 0 = bias only, 1 = bias + exact GELU, 2 = bias + residual add
template<int EPI>
__global__ void sgemm_kernel(const float* __restrict__ A,
                             const float* __restrict__ B,
                             const float* __restrict__ bias,
                             const float* __restrict__ resid,
                             float* __restrict__ C,
                             int M, int N, int K) {
    constexpr int BM = 128, BN = 128, BK = 8, TM = 8, TN = 8;
    __shared__ float As[BK][BM];
    __shared__ float Bs[BK][BN];

    const int tid = threadIdx.x;
    const int bx = blockIdx.x;   // over N
    const int by = blockIdx.y;   // over M
    const int tx = tid % 16;
    const int ty = tid / 16;

    const float* Ab = A + (size_t)by * BM * K;
    const float* Bb = B + (size_t)bx * BN;

    const int aRow = tid >> 1;          // 0..127
    const int aCol = (tid & 1) * 4;     // 0 or 4
    const int bRow = tid >> 5;          // 0..7
    const int bCol = (tid & 31) * 4;    // 0..124

    float acc[TM][TN];
    #pragma unroll
    for (int i = 0; i < TM; i++)
        #pragma unroll
        for (int j = 0; j < TN; j++) acc[i][j] = 0.f;

    for (int k0 = 0; k0 < K; k0 += BK) {
        float4 av = *(const float4*)(Ab + (size_t)aRow * K + k0 + aCol);
        As[aCol + 0][aRow] = av.x;
        As[aCol + 1][aRow] = av.y;
        As[aCol + 2][aRow] = av.z;
        As[aCol + 3][aRow] = av.w;
        float4 bv = *(const float4*)(Bb + (size_t)(k0 + bRow) * N + bCol);
        *(float4*)(&Bs[bRow][bCol]) = bv;
        __syncthreads();

        #pragma unroll
        for (int k = 0; k < BK; k++) {
            float ra[TM], rb[TN];
            #pragma unroll
            for (int i = 0; i < TM; i++) ra[i] = As[k][ty * TM + i];
            float4 b0 = *(const float4*)(&Bs[k][tx * TN]);
            float4 b1 = *(const float4*)(&Bs[k][tx * TN + 4]);
            rb[0] = b0.x; rb[1] = b0.y; rb[2] = b0.z; rb[3] = b0.w;
            rb[4] = b1.x; rb[5] = b1.y; rb[6] = b1.z; rb[7] = b1.w;
            #pragma unroll
            for (int i = 0; i < TM; i++)
                #pragma unroll
                for (int j = 0; j < TN; j++)
                    acc[i][j] += ra[i] * rb[j];
        }
        __syncthreads();
    }

    const int cRow0 = by * BM + ty * TM;
    const int cCol0 = bx * BN + tx * TN;
    #pragma unroll
    for (int i = 0; i < TM; i++) {
        float* crow = C + (size_t)(cRow0 + i) * N + cCol0;
        #pragma unroll
        for (int j = 0; j < TN; j++) {
            float v = acc[i][j] + bias[cCol0 + j];
            if (EPI == 1) {
                v = 0.5f * v * (1.f + erff(v * 0.70710678118654752f));
            } else if (EPI == 2) {
                v += resid[(size_t)(cRow0 + i) * N + cCol0 + j];
            }
            crow[j] = v;
        }
    }
}

// ---------------- RoPE on q and k slices of qkv ----------------
// qkv layout: [S, 3*D]; q = [0,D), k = [D,2D), v = [2D,3D); head h dims h*64..h*64+63
// cos/sin: [S, 64].  out[d] = x[d]*cos[d] - x[d+32]*sin[d] (d<32)
//                    out[d+32] = x[d+32]*cos[d+32] + x[d]*sin[d+32]
__global__ void rope_kernel(float* __restrict__ qkv,
                            const float* __restrict__ cosp,
                            const float* __restrict__ sinp) {
    int idx = blockIdx.x * blockDim.x + threadIdx.x;  // S*H*32
    if (idx >= S_LEN * H_NUM * 32) return;
    const int d = idx & 31;
    const int h = (idx >> 5) & (H_NUM - 1);
    const int s = idx >> (5 + 4);

    const float c1 = cosp[s * 64 + d];
    const float c2 = cosp[s * 64 + d + 32];
    const float s1 = sinp[s * 64 + d];
    const float s2 = sinp[s * 64 + d + 32];

    size_t base = (size_t)s * (3 * D_DIM) + h * HD_DIM + d;
    // q
    float q1 = qkv[base], q2 = qkv[base + 32];
    qkv[base]      = q1 * c1 - q2 * s1;
    qkv[base + 32] = q2 * c2 + q1 * s2;
    // k
    float k1 = qkv[base + D_DIM], k2 = qkv[base + D_DIM + 32];
    qkv[base + D_DIM]      = k1 * c1 - k2 * s1;
    qkv[base + D_DIM + 32] = k2 * c2 + k1 * s2;
}

// ---------------- attention: one block per (query row, head) ----------------
// segment-local softmax(QK^T * scale) @ V
__global__ void attn_kernel(const float* __restrict__ qkv,
                            const int* __restrict__ cu,
                            float* __restrict__ ao) {
    const int s  = blockIdx.x;
    const int hh = blockIdx.y;
    const int tid = threadIdx.x;   // 128 threads

    __shared__ int seg_bounds[2];
    if (tid == 0) {
        int st = 0, en = S_LEN;
        #pragma unroll
        for (int i = 0; i < NSEG; i++) {
            int a = cu[i], b = cu[i + 1];
            if (s >= a && s < b) { st = a; en = b; }
        }
        seg_bounds[0] = st; seg_bounds[1] = en;
    }
    __shared__ float q_s[HD_DIM];
    const float* qrow = qkv + (size_t)s * (3 * D_DIM) + hh * HD_DIM;
    if (tid < HD_DIM) q_s[tid] = qrow[tid];
    __syncthreads();
    const int start = seg_bounds[0];
    const int L = seg_bounds[1] - seg_bounds[0];

    __shared__ float sc[2048];
    __shared__ float red[128];

    // scores
    const float scale = 0.125f;  // 1/sqrt(64)
    for (int j = tid; j < L; j += 128) {
        const float* krow = qkv + (size_t)(start + j) * (3 * D_DIM) + D_DIM + hh * HD_DIM;
        float acc = 0.f;
        #pragma unroll
        for (int d = 0; d < HD_DIM; d++) acc += q_s[d] * krow[d];
        sc[j] = acc * scale;
    }
    __syncthreads();

    // max
    float m = -3.4e38f;
    for (int j = tid; j < L; j += 128) m = fmaxf(m, sc[j]);
    red[tid] = m; __syncthreads();
    for (int o = 64; o > 0; o >>= 1) { if (tid < o) red[tid] = fmaxf(red[tid], red[tid + o]); __syncthreads(); }
    const float mx = red[0];
    __syncthreads();

    // exp + sum
    float sum = 0.f;
    for (int j = tid; j < L; j += 128) {
        float e = expf(sc[j] - mx);
        sc[j] = e;
        sum += e;
    }
    red[tid] = sum; __syncthreads();
    for (int o = 64; o > 0; o >>= 1) { if (tid < o) red[tid] += red[tid + o]; __syncthreads(); }
    const float inv = 1.f / red[0];
    __syncthreads();

    // PV: 128 threads = 2 halves x 64 dims
    const int d = tid & 63;
    const int half = tid >> 6;
    float acc = 0.f;
    for (int j = half; j < L; j += 2)
        acc += sc[j] * qkv[(size_t)(start + j) * (3 * D_DIM) + 2 * D_DIM + hh * HD_DIM + d];
    red[tid] = acc; __syncthreads();
    if (tid < 64)
        ao[(size_t)s * D_DIM + hh * HD_DIM + tid] = (red[tid] + red[tid + 64]) * inv;
}

// ---------------- driver ----------------
extern "C" void kernel_launch(void* const* d_in, const int* in_sizes, int n_in,
                              void* d_out, int out_size) {
    const float* hidden = (const float*)d_in[0];
    const int*   cu     = (const int*)d_in[1];
    const float* cosp   = (const float*)d_in[2];
    const float* sinp   = (const float*)d_in[3];
    const float* ln1_g  = (const float*)d_in[4];
    const float* ln1_b  = (const float*)d_in[5];
    const float* qkv_w  = (const float*)d_in[6];
    const float* qkv_b  = (const float*)d_in[7];
    const float* proj_w = (const float*)d_in[8];
    const float* proj_b = (const float*)d_in[9];
    const float* ln2_g  = (const float*)d_in[10];
    const float* ln2_b  = (const float*)d_in[11];
    const float* fc1_w  = (const float*)d_in[12];
    const float* fc1_b  = (const float*)d_in[13];
    const float* fc2_w  = (const float*)d_in[14];
    const float* fc2_b  = (const float*)d_in[15];

    float* x = (float*)d_out;   // running residual stream

    float *h, *qkv, *ao, *ff;
    cudaGetSymbolAddress((void**)&h,   g_h);
    cudaGetSymbolAddress((void**)&qkv, g_qkv);
    cudaGetSymbolAddress((void**)&ao,  g_ao);
    cudaGetSymbolAddress((void**)&ff,  g_ff);

    // x = hidden_states
    cudaMemcpyAsync(x, hidden, (size_t)S_LEN * D_DIM * sizeof(float),
                    cudaMemcpyDeviceToDevice);

    for (int i = 0; i < DEPTH; i++) {
        const float* qw = qkv_w  + (size_t)i * D_DIM * 3 * D_DIM;
        const float* qb = qkv_b  + (size_t)i * 3 * D_DIM;
        const float* pw = proj_w + (size_t)i * D_DIM * D_DIM;
        const float* pb = proj_b + (size_t)i * D_DIM;
        const float* f1w = fc1_w + (size_t)i * D_DIM * FF_DIM;
        const float* f1b = fc1_b + (size_t)i * FF_DIM;
        const float* f2w = fc2_w + (size_t)i * FF_DIM * D_DIM;
        const float* f2b = fc2_b + (size_t)i * D_DIM;

        // h = LN1(x)
        ln_kernel<<<S_LEN, 256>>>(x, ln1_g + (size_t)i * D_DIM, ln1_b + (size_t)i * D_DIM, h);

        // qkv = h @ qkv_w + qkv_b
        {
            dim3 grid(3 * D_DIM / 128, S_LEN / 128);
            sgemm_kernel<0><<<grid, 256>>>(h, qw, qb, nullptr, qkv, S_LEN, 3 * D_DIM, D_DIM);
        }

        // RoPE on q, k
        {
            int total = S_LEN * H_NUM * 32;
            rope_kernel<<<(total + 255) / 256, 256>>>(qkv, cosp, sinp);
        }

        // ao = attention(qkv)
        {
            dim3 grid(S_LEN, H_NUM);
            attn_kernel<<<grid, 128>>>(qkv, cu, ao);
        }

        // x = x + ao @ proj_w + proj_b
        {
            dim3 grid(D_DIM / 128, S_LEN / 128);
            sgemm_kernel<2><<<grid, 256>>>(ao, pw, pb, x, x, S_LEN, D_DIM, D_DIM);
        }

        // h = LN2(x)
        ln_kernel<<<S_LEN, 256>>>(x, ln2_g + (size_t)i * D_DIM, ln2_b + (size_t)i * D_DIM, h);

        // ff = gelu(h @ fc1_w + fc1_b)
        {
            dim3 grid(FF_DIM / 128, S_LEN / 128);
            sgemm_kernel<1><<<grid, 256>>>(h, f1w, f1b, nullptr, ff, S_LEN, FF_DIM, D_DIM);
        }

        // x = x + ff @ fc2_w + fc2_b
        {
            dim3 grid(D_DIM / 128, S_LEN / 128);
            sgemm_kernel<2><<<grid, 256>>>(ff, f2w, f2b, x, x, S_LEN, D_DIM, FF_DIM);
        }
    }
}

// round 2
// speedup vs baseline: 6.4079x; 6.4079x over previous
#include <cuda_runtime.h>
#include <cuda_bf16.h>
#include <math.h>
#include <stdint.h>

#define S_LEN 2048
#define D_DIM 1024
#define H_NUM 16
#define HD_DIM 64
#define FF_DIM 4096
#define DEPTH 2
#define NSEG 4
#define EPS 1e-6f

// ---------------- scratch (device globals; allocation-free) ----------------
__device__ float g_h  [S_LEN * D_DIM];        // LN output
__device__ float g_qkv[S_LEN * 3 * D_DIM];    // qkv projection
__device__ float g_ao [S_LEN * D_DIM];        // attention output
__device__ float g_ff [S_LEN * FF_DIM];       // fc1 output

// ---------------- helpers ----------------
__device__ __forceinline__ uint32_t f2tf32(float f) {
    uint32_t r;
    asm("cvt.rna.tf32.f32 %0, %1;" : "=r"(r) : "f"(f));
    return r;
}

__device__ __forceinline__ void mma_tf32(float* d,
                                         uint32_t a0, uint32_t a1, uint32_t a2, uint32_t a3,
                                         uint32_t b0, uint32_t b1) {
    asm volatile(
        "mma.sync.aligned.m16n8k8.row.col.f32.tf32.tf32.f32 "
        "{%0,%1,%2,%3}, {%4,%5,%6,%7}, {%8,%9}, {%0,%1,%2,%3};\n"
        : "+f"(d[0]), "+f"(d[1]), "+f"(d[2]), "+f"(d[3])
        : "r"(a0), "r"(a1), "r"(a2), "r"(a3), "r"(b0), "r"(b1));
}

// ---------------- LayerNorm: one block per row ----------------
__global__ void ln_kernel(const float* __restrict__ x,
                          const float* __restrict__ g,
                          const float* __restrict__ b,
                          float* __restrict__ out) {
    const int row = blockIdx.x;
    const int tid = threadIdx.x;                // 256 threads
    const float* xr = x + (size_t)row * D_DIM;
    __shared__ float red[256];

    float s = 0.f;
    for (int i = tid; i < D_DIM; i += 256) s += xr[i];
    red[tid] = s; __syncthreads();
    for (int o = 128; o > 0; o >>= 1) { if (tid < o) red[tid] += red[tid + o]; __syncthreads(); }
    const float mean = red[0] * (1.f / D_DIM);
    __syncthreads();

    float v = 0.f;
    for (int i = tid; i < D_DIM; i += 256) { float d = xr[i] - mean; v += d * d; }
    red[tid] = v; __syncthreads();
    for (int o = 128; o > 0; o >>= 1) { if (tid < o) red[tid] += red[tid + o]; __syncthreads(); }
    const float rstd = rsqrtf(red[0] * (1.f / D_DIM) + EPS);

    for (int i = tid; i < D_DIM; i += 256)
        out[(size_t)row * D_DIM + i] = (xr[i] - mean) * rstd * g[i] + b[i];
}

// ---------------- TF32 tensor-core GEMM: 128x128 tile, BK=32, 256 thr -------
// C[M,N] = A[M,K] @ B[K,N] + bias (+ epilogue)
// EPI: 0 = bias only, 1 = bias + exact GELU, 2 = bias + residual add
template<int EPI>
__global__ __launch_bounds__(256, 2)
void gemm_tf32_kernel(const float* __restrict__ A,
                      const float* __restrict__ B,
                      const float* __restrict__ bias,
                      const float* __restrict__ resid,
                      float* __restrict__ C,
                      int M, int N, int K) {
    __shared__ float As[128][36];   // [m][k], pad 4 -> conflict-free frag loads
    __shared__ float Bs[32][136];   // [k][n], pad 8 -> conflict-free frag loads

    const int tid  = threadIdx.x;
    const int lane = tid & 31;
    const int wid  = tid >> 5;
    const int warp_m = wid & 1;     // 2 warps over M (64 each)
    const int warp_n = wid >> 1;    // 4 warps over N (32 each)
    const int g = lane >> 2;        // groupID
    const int t = lane & 3;         // threadID in group

    const int bx = blockIdx.x;      // N tiles
    const int by = blockIdx.y;      // M tiles

    const float* Ag = A + (size_t)by * 128 * K;
    const float* Bg = B + (size_t)bx * 128;

    float acc[4][4][4];
    #pragma unroll
    for (int mi = 0; mi < 4; mi++)
        #pragma unroll
        for (int ni = 0; ni < 4; ni++)
            #pragma unroll
            for (int e = 0; e < 4; e++) acc[mi][ni][e] = 0.f;

    for (int k0 = 0; k0 < K; k0 += 32) {
        // load A tile 128x32 (4 float4 per thread)
        #pragma unroll
        for (int i = 0; i < 4; i++) {
            int id  = tid + 256 * i;
            int row = id >> 3;
            int c4  = (id & 7) * 4;
            float4 v = *(const float4*)(Ag + (size_t)row * K + k0 + c4);
            As[row][c4 + 0] = __uint_as_float(f2tf32(v.x));
            As[row][c4 + 1] = __uint_as_float(f2tf32(v.y));
            As[row][c4 + 2] = __uint_as_float(f2tf32(v.z));
            As[row][c4 + 3] = __uint_as_float(f2tf32(v.w));
        }
        // load B tile 32x128
        #pragma unroll
        for (int i = 0; i < 4; i++) {
            int id  = tid + 256 * i;
            int row = id >> 5;
            int c4  = (id & 31) * 4;
            float4 v = *(const float4*)(Bg + (size_t)(k0 + row) * N + c4);
            Bs[row][c4 + 0] = __uint_as_float(f2tf32(v.x));
            Bs[row][c4 + 1] = __uint_as_float(f2tf32(v.y));
            Bs[row][c4 + 2] = __uint_as_float(f2tf32(v.z));
            Bs[row][c4 + 3] = __uint_as_float(f2tf32(v.w));
        }
        __syncthreads();

        #pragma unroll
        for (int kk = 0; kk < 4; kk++) {
            const int k = kk * 8;
            uint32_t af[4][4], bf[4][2];
            #pragma unroll
            for (int mi = 0; mi < 4; mi++) {
                int r0 = warp_m * 64 + mi * 16 + g;
                af[mi][0] = __float_as_uint(As[r0    ][k + t    ]);
                af[mi][1] = __float_as_uint(As[r0 + 8][k + t    ]);
                af[mi][2] = __float_as_uint(As[r0    ][k + t + 4]);
                af[mi][3] = __float_as_uint(As[r0 + 8][k + t + 4]);
            }
            #pragma unroll
            for (int ni = 0; ni < 4; ni++) {
                int c0 = warp_n * 32 + ni * 8 + g;
                bf[ni][0] = __float_as_uint(Bs[k + t    ][c0]);
                bf[ni][1] = __float_as_uint(Bs[k + t + 4][c0]);
            }
            #pragma unroll
            for (int mi = 0; mi < 4; mi++)
                #pragma unroll
                for (int ni = 0; ni < 4; ni++)
                    mma_tf32(acc[mi][ni], af[mi][0], af[mi][1], af[mi][2], af[mi][3],
                             bf[ni][0], bf[ni][1]);
        }
        __syncthreads();
    }

    // epilogue
    #pragma unroll
    for (int mi = 0; mi < 4; mi++) {
        const int row0 = by * 128 + warp_m * 64 + mi * 16 + g;
        #pragma unroll
        for (int ni = 0; ni < 4; ni++) {
            const int col = bx * 128 + warp_n * 32 + ni * 8 + 2 * t;
            #pragma unroll
            for (int half = 0; half < 2; half++) {
                const int r = row0 + half * 8;
                #pragma unroll
                for (int e = 0; e < 2; e++) {
                    float v = acc[mi][ni][half * 2 + e] + bias[col + e];
                    if (EPI == 1) {
                        v = 0.5f * v * (1.f + erff(v * 0.70710678118654752f));
                    } else if (EPI == 2) {
                        v += resid[(size_t)r * N + col + e];
                    }
                    C[(size_t)r * N + col + e] = v;
                }
            }
        }
    }
}

// ---------------- RoPE on q and k slices of qkv ----------------
__global__ void rope_kernel(float* __restrict__ qkv,
                            const float* __restrict__ cosp,
                            const float* __restrict__ sinp) {
    int idx = blockIdx.x * blockDim.x + threadIdx.x;  // S*H*32
    if (idx >= S_LEN * H_NUM * 32) return;
    const int d = idx & 31;
    const int h = (idx >> 5) & (H_NUM - 1);
    const int s = idx >> (5 + 4);

    const float c1 = cosp[s * 64 + d];
    const float c2 = cosp[s * 64 + d + 32];
    const float s1 = sinp[s * 64 + d];
    const float s2 = sinp[s * 64 + d + 32];

    size_t base = (size_t)s * (3 * D_DIM) + h * HD_DIM + d;
    float q1 = qkv[base], q2 = qkv[base + 32];
    qkv[base]      = q1 * c1 - q2 * s1;
    qkv[base + 32] = q2 * c2 + q1 * s2;
    float k1 = qkv[base + D_DIM], k2 = qkv[base + D_DIM + 32];
    qkv[base + D_DIM]      = k1 * c1 - k2 * s1;
    qkv[base + D_DIM + 32] = k2 * c2 + k1 * s2;
}

// ---------------- flash attention: block = (64 q-rows, head) ----------------
// 256 threads = 64 rows x 4 quads. Each thread owns dims {4q+16*ii+0..3}.
__global__ __launch_bounds__(256)
void attn_kernel(const float* __restrict__ qkv,
                 const int* __restrict__ cu,
                 float* __restrict__ ao) {
    const int h  = blockIdx.y;
    const int s0 = blockIdx.x * 64;
    const int tid = threadIdx.x;
    const int r = tid >> 2;     // local q row 0..63
    const int q = tid & 3;      // quad

    __shared__ float Ks[64][68];
    __shared__ float Vs[64][68];
    float (*Ps)[68] = Ks;       // P aliases K buffer (guarded by syncs)

    // segment bounds (blocks never straddle: 64 | 512)
    int start = 0, len = S_LEN;
    #pragma unroll
    for (int i = 0; i < NSEG; i++) {
        int a = cu[i], b = cu[i + 1];
        if (s0 >= a && s0 < b) { start = a; len = b - a; }
    }

    // Q into registers, pre-scaled
    float qreg[16];
    {
        const float* qp = qkv + (size_t)(s0 + r) * (3 * D_DIM) + h * HD_DIM;
        #pragma unroll
        for (int ii = 0; ii < 4; ii++) {
            float4 v = *(const float4*)(qp + 4 * q + 16 * ii);
            qreg[ii * 4 + 0] = v.x * 0.125f;
            qreg[ii * 4 + 1] = v.y * 0.125f;
            qreg[ii * 4 + 2] = v.z * 0.125f;
            qreg[ii * 4 + 3] = v.w * 0.125f;
        }
    }

    float m_run = -3.4e38f, l_run = 0.f;
    float out[16];
    #pragma unroll
    for (int i = 0; i < 16; i++) out[i] = 0.f;

    const int nch = len >> 6;
    for (int c = 0; c < nch; c++) {
        const int kbase = start + c * 64;
        // load K, V chunks
        #pragma unroll
        for (int i = 0; i < 4; i++) {
            int id  = tid + 256 * i;
            int row = id >> 4;
            int c4  = (id & 15) * 4;
            const float* base = qkv + (size_t)(kbase + row) * (3 * D_DIM) + h * HD_DIM;
            *(float4*)&Ks[row][c4] = *(const float4*)(base + D_DIM + c4);
            *(float4*)&Vs[row][c4] = *(const float4*)(base + 2 * D_DIM + c4);
        }
        __syncthreads();

        // scores: quad cooperates on each key
        float sreg[16];
        #pragma unroll 4
        for (int j = 0; j < 64; j++) {
            float acc = 0.f;
            #pragma unroll
            for (int ii = 0; ii < 4; ii++) {
                float4 kv = *(const float4*)&Ks[j][4 * q + 16 * ii];
                acc += qreg[ii * 4 + 0] * kv.x + qreg[ii * 4 + 1] * kv.y
                     + qreg[ii * 4 + 2] * kv.z + qreg[ii * 4 + 3] * kv.w;
            }
            acc += __shfl_xor_sync(0xffffffffu, acc, 1);
            acc += __shfl_xor_sync(0xffffffffu, acc, 2);
            if ((j & 3) == q) sreg[j >> 2] = acc;
        }
        __syncthreads();   // done reading Ks before P overwrites it

        // online softmax update
        float mloc = -3.4e38f;
        #pragma unroll
        for (int i = 0; i < 16; i++) mloc = fmaxf(mloc, sreg[i]);
        mloc = fmaxf(mloc, __shfl_xor_sync(0xffffffffu, mloc, 1));
        mloc = fmaxf(mloc, __shfl_xor_sync(0xffffffffu, mloc, 2));
        const float m_new = fmaxf(m_run, mloc);
        const float factor = __expf(m_run - m_new);
        float lloc = 0.f;
        #pragma unroll
        for (int i = 0; i < 16; i++) {
            float p = __expf(sreg[i] - m_new);
            lloc += p;
            Ps[r][q + 4 * i] = p;
        }
        lloc += __shfl_xor_sync(0xffffffffu, lloc, 1);
        lloc += __shfl_xor_sync(0xffffffffu, lloc, 2);
        l_run = l_run * factor + lloc;
        m_run = m_new;
        #pragma unroll
        for (int i = 0; i < 16; i++) out[i] *= factor;
        __syncwarp();      // P row written/read within same warp

        // PV
        #pragma unroll 4
        for (int j = 0; j < 64; j++) {
            float p = Ps[r][j];
            #pragma unroll
            for (int ii = 0; ii < 4; ii++) {
                float4 vv = *(const float4*)&Vs[j][4 * q + 16 * ii];
                out[ii * 4 + 0] += p * vv.x;
                out[ii * 4 + 1] += p * vv.y;
                out[ii * 4 + 2] += p * vv.z;
                out[ii * 4 + 3] += p * vv.w;
            }
        }
        __syncthreads();   // before next chunk overwrites Ks/Vs
    }

    const float inv = 1.f / l_run;
    float* op = ao + (size_t)(s0 + r) * D_DIM + h * HD_DIM;
    #pragma unroll
    for (int ii = 0; ii < 4; ii++) {
        float4 v;
        v.x = out[ii * 4 + 0] * inv;
        v.y = out[ii * 4 + 1] * inv;
        v.z = out[ii * 4 + 2] * inv;
        v.w = out[ii * 4 + 3] * inv;
        *(float4*)(op + 4 * q + 16 * ii) = v;
    }
}

// ---------------- driver ----------------
extern "C" void kernel_launch(void* const* d_in, const int* in_sizes, int n_in,
                              void* d_out, int out_size) {
    const float* hidden = (const float*)d_in[0];
    const int*   cu     = (const int*)d_in[1];
    const float* cosp   = (const float*)d_in[2];
    const float* sinp   = (const float*)d_in[3];
    const float* ln1_g  = (const float*)d_in[4];
    const float* ln1_b  = (const float*)d_in[5];
    const float* qkv_w  = (const float*)d_in[6];
    const float* qkv_b  = (const float*)d_in[7];
    const float* proj_w = (const float*)d_in[8];
    const float* proj_b = (const float*)d_in[9];
    const float* ln2_g  = (const float*)d_in[10];
    const float* ln2_b  = (const float*)d_in[11];
    const float* fc1_w  = (const float*)d_in[12];
    const float* fc1_b  = (const float*)d_in[13];
    const float* fc2_w  = (const float*)d_in[14];
    const float* fc2_b  = (const float*)d_in[15];

    float* x = (float*)d_out;   // running residual stream

    float *h, *qkv, *ao, *ff;
    cudaGetSymbolAddress((void**)&h,   g_h);
    cudaGetSymbolAddress((void**)&qkv, g_qkv);
    cudaGetSymbolAddress((void**)&ao,  g_ao);
    cudaGetSymbolAddress((void**)&ff,  g_ff);

    cudaMemcpyAsync(x, hidden, (size_t)S_LEN * D_DIM * sizeof(float),
                    cudaMemcpyDeviceToDevice);

    for (int i = 0; i < DEPTH; i++) {
        const float* qw  = qkv_w  + (size_t)i * D_DIM * 3 * D_DIM;
        const float* qb  = qkv_b  + (size_t)i * 3 * D_DIM;
        const float* pw  = proj_w + (size_t)i * D_DIM * D_DIM;
        const float* pb  = proj_b + (size_t)i * D_DIM;
        const float* f1w = fc1_w  + (size_t)i * D_DIM * FF_DIM;
        const float* f1b = fc1_b  + (size_t)i * FF_DIM;
        const float* f2w = fc2_w  + (size_t)i * FF_DIM * D_DIM;
        const float* f2b = fc2_b  + (size_t)i * D_DIM;

        ln_kernel<<<S_LEN, 256>>>(x, ln1_g + (size_t)i * D_DIM, ln1_b + (size_t)i * D_DIM, h);

        {   // qkv = h @ qkv_w + qkv_b
            dim3 grid(3 * D_DIM / 128, S_LEN / 128);
            gemm_tf32_kernel<0><<<grid, 256>>>(h, qw, qb, nullptr, qkv, S_LEN, 3 * D_DIM, D_DIM);
        }

        {   // RoPE
            int total = S_LEN * H_NUM * 32;
            rope_kernel<<<(total + 255) / 256, 256>>>(qkv, cosp, sinp);
        }

        {   // attention
            dim3 grid(S_LEN / 64, H_NUM);
            attn_kernel<<<grid, 256>>>(qkv, cu, ao);
        }

        {   // x += ao @ proj_w + proj_b
            dim3 grid(D_DIM / 128, S_LEN / 128);
            gemm_tf32_kernel<2><<<grid, 256>>>(ao, pw, pb, x, x, S_LEN, D_DIM, D_DIM);
        }

        ln_kernel<<<S_LEN, 256>>>(x, ln2_g + (size_t)i * D_DIM, ln2_b + (size_t)i * D_DIM, h);

        {   // ff = gelu(h @ fc1_w + fc1_b)
            dim3 grid(FF_DIM / 128, S_LEN / 128);
            gemm_tf32_kernel<1><<<grid, 256>>>(h, f1w, f1b, nullptr, ff, S_LEN, FF_DIM, D_DIM);
        }

        {   // x += ff @ fc2_w + fc2_b
            dim3 grid(D_DIM / 128, S_LEN / 128);
            gemm_tf32_kernel<2><<<grid, 256>>>(ff, f2w, f2b, x, x, S_LEN, D_DIM, FF_DIM);
        }
    }
}

// round 4
// speedup vs baseline: 10.4746x; 1.6346x over previous
#include <cuda_runtime.h>
#include <cuda_bf16.h>
#include <math.h>
#include <stdint.h>

#define S_LEN 2048
#define D_DIM 1024
#define H_NUM 16
#define HD_DIM 64
#define FF_DIM 4096
#define DEPTH 2
#define NSEG 4
#define EPS 1e-6f

// ---------------- scratch (device globals; allocation-free) ----------------
__device__ float g_h  [S_LEN * D_DIM];        // LN output
__device__ float g_qkv[S_LEN * 3 * D_DIM];    // qkv projection
__device__ float g_ao [S_LEN * D_DIM];        // attention output
__device__ float g_ff [S_LEN * FF_DIM];       // fc1 output

// ---------------- helpers ----------------
__device__ __forceinline__ uint32_t f2tf32(float f) {
    uint32_t r;
    asm("cvt.rna.tf32.f32 %0, %1;" : "=r"(r) : "f"(f));
    return r;
}

__device__ __forceinline__ void mma_tf32(float* d,
                                         uint32_t a0, uint32_t a1, uint32_t a2, uint32_t a3,
                                         uint32_t b0, uint32_t b1) {
    asm volatile(
        "mma.sync.aligned.m16n8k8.row.col.f32.tf32.tf32.f32 "
        "{%0,%1,%2,%3}, {%4,%5,%6,%7}, {%8,%9}, {%0,%1,%2,%3};\n"
        : "+f"(d[0]), "+f"(d[1]), "+f"(d[2]), "+f"(d[3])
        : "r"(a0), "r"(a1), "r"(a2), "r"(a3), "r"(b0), "r"(b1));
}

__device__ __forceinline__ void cp16(void* dst, const void* src) {
    uint32_t d = (uint32_t)__cvta_generic_to_shared(dst);
    asm volatile("cp.async.cg.shared.global [%0], [%1], 16;\n" :: "r"(d), "l"(src));
}
__device__ __forceinline__ void cp_commit() {
    asm volatile("cp.async.commit_group;\n");
}

// ---------------- LayerNorm: one block per row ----------------
__global__ void ln_kernel(const float* __restrict__ x,
                          const float* __restrict__ g,
                          const float* __restrict__ b,
                          float* __restrict__ out) {
    const int row = blockIdx.x;
    const int tid = threadIdx.x;                // 256 threads
    const float* xr = x + (size_t)row * D_DIM;
    __shared__ float red[256];

    float s = 0.f;
    for (int i = tid; i < D_DIM; i += 256) s += xr[i];
    red[tid] = s; __syncthreads();
    for (int o = 128; o > 0; o >>= 1) { if (tid < o) red[tid] += red[tid + o]; __syncthreads(); }
    const float mean = red[0] * (1.f / D_DIM);
    __syncthreads();

    float v = 0.f;
    for (int i = tid; i < D_DIM; i += 256) { float d = xr[i] - mean; v += d * d; }
    red[tid] = v; __syncthreads();
    for (int o = 128; o > 0; o >>= 1) { if (tid < o) red[tid] += red[tid + o]; __syncthreads(); }
    const float rstd = rsqrtf(red[0] * (1.f / D_DIM) + EPS);

    for (int i = tid; i < D_DIM; i += 256)
        out[(size_t)row * D_DIM + i] = (xr[i] - mean) * rstd * g[i] + b[i];
}

// ------------- TF32 GEMM: 128x128 tile, BK=16, cp.async double buffer -------
// RNA tf32 conversion applied to fragments AFTER the shared-memory load.
// EPI: 0 = bias only, 1 = bias + exact GELU, 2 = bias + residual add
template<int EPI>
__global__ __launch_bounds__(256)
void gemm_tf32_kernel(const float* __restrict__ A,
                      const float* __restrict__ B,
                      const float* __restrict__ bias,
                      const float* __restrict__ resid,
                      float* __restrict__ C,
                      int M, int N, int K) {
    __shared__ float As[2][128][20];
    __shared__ float Bs[2][16][136];

    const int tid  = threadIdx.x;
    const int lane = tid & 31;
    const int wid  = tid >> 5;
    const int warp_m = wid & 1;
    const int warp_n = wid >> 1;
    const int g = lane >> 2;
    const int t = lane & 3;

    const int bx = blockIdx.x;
    const int by = blockIdx.y;

    const float* Ag = A + (size_t)by * 128 * K;
    const float* Bg = B + (size_t)bx * 128;

    float acc[4][4][4];
    #pragma unroll
    for (int mi = 0; mi < 4; mi++)
        #pragma unroll
        for (int ni = 0; ni < 4; ni++)
            #pragma unroll
            for (int e = 0; e < 4; e++) acc[mi][ni][e] = 0.f;

    const int NIT = K >> 4;

    {
        #pragma unroll
        for (int i = 0; i < 2; i++) {
            int id = tid + 256 * i;
            int r = id >> 2, c4 = (id & 3) * 4;
            cp16(&As[0][r][c4], Ag + (size_t)r * K + c4);
        }
        #pragma unroll
        for (int i = 0; i < 2; i++) {
            int id = tid + 256 * i;
            int r = id >> 5, c4 = (id & 31) * 4;
            cp16(&Bs[0][r][c4], Bg + (size_t)r * N + c4);
        }
        cp_commit();
    }

    #pragma unroll 1
    for (int it = 0; it < NIT; it++) {
        const int buf = it & 1;
        if (it + 1 < NIT) {
            const int k0 = (it + 1) << 4;
            #pragma unroll
            for (int i = 0; i < 2; i++) {
                int id = tid + 256 * i;
                int r = id >> 2, c4 = (id & 3) * 4;
                cp16(&As[buf ^ 1][r][c4], Ag + (size_t)r * K + k0 + c4);
            }
            #pragma unroll
            for (int i = 0; i < 2; i++) {
                int id = tid + 256 * i;
                int r = id >> 5, c4 = (id & 31) * 4;
                cp16(&Bs[buf ^ 1][r][c4], Bg + (size_t)(k0 + r) * N + c4);
            }
            cp_commit();
            asm volatile("cp.async.wait_group 1;\n");
        } else {
            asm volatile("cp.async.wait_group 0;\n");
        }
        __syncthreads();

        #pragma unroll
        for (int ks = 0; ks < 2; ks++) {
            const int k = ks * 8;
            uint32_t af[4][4], bf[4][2];
            #pragma unroll
            for (int mi = 0; mi < 4; mi++) {
                int r0 = warp_m * 64 + mi * 16 + g;
                af[mi][0] = f2tf32(As[buf][r0    ][k + t    ]);
                af[mi][1] = f2tf32(As[buf][r0 + 8][k + t    ]);
                af[mi][2] = f2tf32(As[buf][r0    ][k + t + 4]);
                af[mi][3] = f2tf32(As[buf][r0 + 8][k + t + 4]);
            }
            #pragma unroll
            for (int ni = 0; ni < 4; ni++) {
                int c0 = warp_n * 32 + ni * 8 + g;
                bf[ni][0] = f2tf32(Bs[buf][k + t    ][c0]);
                bf[ni][1] = f2tf32(Bs[buf][k + t + 4][c0]);
            }
            #pragma unroll
            for (int mi = 0; mi < 4; mi++)
                #pragma unroll
                for (int ni = 0; ni < 4; ni++)
                    mma_tf32(acc[mi][ni], af[mi][0], af[mi][1], af[mi][2], af[mi][3],
                             bf[ni][0], bf[ni][1]);
        }
        __syncthreads();
    }

    #pragma unroll
    for (int mi = 0; mi < 4; mi++) {
        const int row0 = by * 128 + warp_m * 64 + mi * 16 + g;
        #pragma unroll
        for (int ni = 0; ni < 4; ni++) {
            const int col = bx * 128 + warp_n * 32 + ni * 8 + 2 * t;
            #pragma unroll
            for (int half = 0; half < 2; half++) {
                const int r = row0 + half * 8;
                #pragma unroll
                for (int e = 0; e < 2; e++) {
                    float v = acc[mi][ni][half * 2 + e] + bias[col + e];
                    if (EPI == 1) {
                        v = 0.5f * v * (1.f + erff(v * 0.70710678118654752f));
                    } else if (EPI == 2) {
                        v += resid[(size_t)r * N + col + e];
                    }
                    C[(size_t)r * N + col + e] = v;
                }
            }
        }
    }
}

// ---------------- RoPE on q and k slices of qkv ----------------
__global__ void rope_kernel(float* __restrict__ qkv,
                            const float* __restrict__ cosp,
                            const float* __restrict__ sinp) {
    int idx = blockIdx.x * blockDim.x + threadIdx.x;  // S*H*32
    if (idx >= S_LEN * H_NUM * 32) return;
    const int d = idx & 31;
    const int h = (idx >> 5) & (H_NUM - 1);
    const int s = idx >> (5 + 4);

    const float c1 = cosp[s * 64 + d];
    const float c2 = cosp[s * 64 + d + 32];
    const float s1 = sinp[s * 64 + d];
    const float s2 = sinp[s * 64 + d + 32];

    size_t base = (size_t)s * (3 * D_DIM) + h * HD_DIM + d;
    float q1 = qkv[base], q2 = qkv[base + 32];
    qkv[base]      = q1 * c1 - q2 * s1;
    qkv[base + 32] = q2 * c2 + q1 * s2;
    float k1 = qkv[base + D_DIM], k2 = qkv[base + D_DIM + 32];
    qkv[base + D_DIM]      = k1 * c1 - k2 * s1;
    qkv[base + D_DIM + 32] = k2 * c2 + k1 * s2;
}

// ---------- tensor-core flash attention: block = (128 q-rows, head) ---------
// 8 warps; warp w owns output rows 16w..16w+15 for both QK^T and PV.
// All mma inputs RNA-rounded to tf32.
__global__ __launch_bounds__(256)
void attn_kernel(const float* __restrict__ qkv,
                 const int* __restrict__ cu,
                 float* __restrict__ ao) {
    const int h  = blockIdx.y;
    const int s0 = blockIdx.x * 128;
    const int tid  = threadIdx.x;
    const int lane = tid & 31;
    const int wid  = tid >> 5;
    const int g = lane >> 2;
    const int t = lane & 3;

    __shared__ float Ks[32][68];
    __shared__ float Vs[32][72];
    __shared__ float Ps[128][36];

    int start = 0, len = S_LEN;
    #pragma unroll
    for (int i = 0; i < NSEG; i++) {
        int a = cu[i], b = cu[i + 1];
        if (s0 >= a && s0 < b) { start = a; len = b - a; }
    }

    // Q fragments, pre-scaled then RNA-rounded once
    uint32_t qf[8][4];
    {
        const float* q0 = qkv + (size_t)(s0 + wid * 16 + g) * (3 * D_DIM) + h * HD_DIM;
        const float* q8 = q0 + 8 * (3 * D_DIM);
        #pragma unroll
        for (int ks = 0; ks < 8; ks++) {
            qf[ks][0] = f2tf32(q0[8 * ks + t]     * 0.125f);
            qf[ks][1] = f2tf32(q8[8 * ks + t]     * 0.125f);
            qf[ks][2] = f2tf32(q0[8 * ks + t + 4] * 0.125f);
            qf[ks][3] = f2tf32(q8[8 * ks + t + 4] * 0.125f);
        }
    }

    float m0 = -3.4e38f, m1 = -3.4e38f, l0 = 0.f, l1 = 0.f;
    float out[8][4];
    #pragma unroll
    for (int n = 0; n < 8; n++)
        #pragma unroll
        for (int e = 0; e < 4; e++) out[n][e] = 0.f;

    const int pr = wid * 16;
    const int nch = len >> 5;
    for (int c = 0; c < nch; c++) {
        const int kb = start + c * 32;
        // K,V smem stores with RNA tf32 rounding (free on the LDG->STS path)
        #pragma unroll
        for (int i = 0; i < 2; i++) {
            int id = tid + 256 * i;
            int r = id >> 4, c4 = (id & 15) * 4;
            const float* base = qkv + (size_t)(kb + r) * (3 * D_DIM) + h * HD_DIM + c4;
            float4 kv = *(const float4*)(base + D_DIM);
            float4 vv = *(const float4*)(base + 2 * D_DIM);
            Ks[r][c4 + 0] = __uint_as_float(f2tf32(kv.x));
            Ks[r][c4 + 1] = __uint_as_float(f2tf32(kv.y));
            Ks[r][c4 + 2] = __uint_as_float(f2tf32(kv.z));
            Ks[r][c4 + 3] = __uint_as_float(f2tf32(kv.w));
            Vs[r][c4 + 0] = __uint_as_float(f2tf32(vv.x));
            Vs[r][c4 + 1] = __uint_as_float(f2tf32(vv.y));
            Vs[r][c4 + 2] = __uint_as_float(f2tf32(vv.z));
            Vs[r][c4 + 3] = __uint_as_float(f2tf32(vv.w));
        }
        __syncthreads();

        // S = Q @ K^T
        float sacc[4][4];
        #pragma unroll
        for (int j = 0; j < 4; j++)
            #pragma unroll
            for (int e = 0; e < 4; e++) sacc[j][e] = 0.f;
        #pragma unroll
        for (int ks = 0; ks < 8; ks++) {
            #pragma unroll
            for (int j = 0; j < 4; j++) {
                uint32_t b0 = __float_as_uint(Ks[8 * j + g][8 * ks + t]);
                uint32_t b1 = __float_as_uint(Ks[8 * j + g][8 * ks + t + 4]);
                mma_tf32(sacc[j], qf[ks][0], qf[ks][1], qf[ks][2], qf[ks][3], b0, b1);
            }
        }

        // online softmax
        float ml0 = -3.4e38f, ml1 = -3.4e38f;
        #pragma unroll
        for (int j = 0; j < 4; j++) {
            ml0 = fmaxf(ml0, fmaxf(sacc[j][0], sacc[j][1]));
            ml1 = fmaxf(ml1, fmaxf(sacc[j][2], sacc[j][3]));
        }
        ml0 = fmaxf(ml0, __shfl_xor_sync(0xffffffffu, ml0, 1));
        ml0 = fmaxf(ml0, __shfl_xor_sync(0xffffffffu, ml0, 2));
        ml1 = fmaxf(ml1, __shfl_xor_sync(0xffffffffu, ml1, 1));
        ml1 = fmaxf(ml1, __shfl_xor_sync(0xffffffffu, ml1, 2));
        const float mn0 = fmaxf(m0, ml0);
        const float mn1 = fmaxf(m1, ml1);
        const float f0 = __expf(m0 - mn0);
        const float f1 = __expf(m1 - mn1);

        float ll0 = 0.f, ll1 = 0.f;
        #pragma unroll
        for (int j = 0; j < 4; j++) {
            float p0 = __expf(sacc[j][0] - mn0);
            float p1 = __expf(sacc[j][1] - mn0);
            float p2 = __expf(sacc[j][2] - mn1);
            float p3 = __expf(sacc[j][3] - mn1);
            ll0 += p0 + p1; ll1 += p2 + p3;
            Ps[pr + g    ][8 * j + 2 * t]     = __uint_as_float(f2tf32(p0));
            Ps[pr + g    ][8 * j + 2 * t + 1] = __uint_as_float(f2tf32(p1));
            Ps[pr + g + 8][8 * j + 2 * t]     = __uint_as_float(f2tf32(p2));
            Ps[pr + g + 8][8 * j + 2 * t + 1] = __uint_as_float(f2tf32(p3));
        }
        ll0 += __shfl_xor_sync(0xffffffffu, ll0, 1);
        ll0 += __shfl_xor_sync(0xffffffffu, ll0, 2);
        ll1 += __shfl_xor_sync(0xffffffffu, ll1, 1);
        ll1 += __shfl_xor_sync(0xffffffffu, ll1, 2);
        l0 = l0 * f0 + ll0;
        l1 = l1 * f1 + ll1;
        m0 = mn0; m1 = mn1;
        #pragma unroll
        for (int n = 0; n < 8; n++) {
            out[n][0] *= f0; out[n][1] *= f0;
            out[n][2] *= f1; out[n][3] *= f1;
        }
        __syncwarp();   // P rows produced & consumed within this warp only

        // out += P @ V
        #pragma unroll
        for (int ks = 0; ks < 4; ks++) {
            uint32_t a0 = __float_as_uint(Ps[pr + g    ][8 * ks + t]);
            uint32_t a1 = __float_as_uint(Ps[pr + g + 8][8 * ks + t]);
            uint32_t a2 = __float_as_uint(Ps[pr + g    ][8 * ks + t + 4]);
            uint32_t a3 = __float_as_uint(Ps[pr + g + 8][8 * ks + t + 4]);
            #pragma unroll
            for (int n = 0; n < 8; n++) {
                uint32_t b0 = __float_as_uint(Vs[8 * ks + t    ][8 * n + g]);
                uint32_t b1 = __float_as_uint(Vs[8 * ks + t + 4][8 * n + g]);
                mma_tf32(out[n], a0, a1, a2, a3, b0, b1);
            }
        }
        __syncthreads();
    }

    const float i0 = 1.f / l0;
    const float i1 = 1.f / l1;
    float* o0 = ao + (size_t)(s0 + pr + g) * D_DIM + h * HD_DIM;
    float* o8 = o0 + 8 * D_DIM;
    #pragma unroll
    for (int n = 0; n < 8; n++) {
        float2 v0 = make_float2(out[n][0] * i0, out[n][1] * i0);
        float2 v1 = make_float2(out[n][2] * i1, out[n][3] * i1);
        *(float2*)(o0 + 8 * n + 2 * t) = v0;
        *(float2*)(o8 + 8 * n + 2 * t) = v1;
    }
}

// ---------------- driver ----------------
extern "C" void kernel_launch(void* const* d_in, const int* in_sizes, int n_in,
                              void* d_out, int out_size) {
    const float* hidden = (const float*)d_in[0];
    const int*   cu     = (const int*)d_in[1];
    const float* cosp   = (const float*)d_in[2];
    const float* sinp   = (const float*)d_in[3];
    const float* ln1_g  = (const float*)d_in[4];
    const float* ln1_b  = (const float*)d_in[5];
    const float* qkv_w  = (const float*)d_in[6];
    const float* qkv_b  = (const float*)d_in[7];
    const float* proj_w = (const float*)d_in[8];
    const float* proj_b = (const float*)d_in[9];
    const float* ln2_g  = (const float*)d_in[10];
    const float* ln2_b  = (const float*)d_in[11];
    const float* fc1_w  = (const float*)d_in[12];
    const float* fc1_b  = (const float*)d_in[13];
    const float* fc2_w  = (const float*)d_in[14];
    const float* fc2_b  = (const float*)d_in[15];

    float* x = (float*)d_out;

    float *h, *qkv, *ao, *ff;
    cudaGetSymbolAddress((void**)&h,   g_h);
    cudaGetSymbolAddress((void**)&qkv, g_qkv);
    cudaGetSymbolAddress((void**)&ao,  g_ao);
    cudaGetSymbolAddress((void**)&ff,  g_ff);

    cudaMemcpyAsync(x, hidden, (size_t)S_LEN * D_DIM * sizeof(float),
                    cudaMemcpyDeviceToDevice);

    for (int i = 0; i < DEPTH; i++) {
        const float* qw  = qkv_w  + (size_t)i * D_DIM * 3 * D_DIM;
        const float* qb  = qkv_b  + (size_t)i * 3 * D_DIM;
        const float* pw  = proj_w + (size_t)i * D_DIM * D_DIM;
        const float* pb  = proj_b + (size_t)i * D_DIM;
        const float* f1w = fc1_w  + (size_t)i * D_DIM * FF_DIM;
        const float* f1b = fc1_b  + (size_t)i * FF_DIM;
        const float* f2w = fc2_w  + (size_t)i * FF_DIM * D_DIM;
        const float* f2b = fc2_b  + (size_t)i * D_DIM;

        ln_kernel<<<S_LEN, 256>>>(x, ln1_g + (size_t)i * D_DIM, ln1_b + (size_t)i * D_DIM, h);

        {
            dim3 grid(3 * D_DIM / 128, S_LEN / 128);
            gemm_tf32_kernel<0><<<grid, 256>>>(h, qw, qb, nullptr, qkv, S_LEN, 3 * D_DIM, D_DIM);
        }

        {
            int total = S_LEN * H_NUM * 32;
            rope_kernel<<<(total + 255) / 256, 256>>>(qkv, cosp, sinp);
        }

        {
            dim3 grid(S_LEN / 128, H_NUM);
            attn_kernel<<<grid, 256>>>(qkv, cu, ao);
        }

        {
            dim3 grid(D_DIM / 128, S_LEN / 128);
            gemm_tf32_kernel<2><<<grid, 256>>>(ao, pw, pb, x, x, S_LEN, D_DIM, D_DIM);
        }

        ln_kernel<<<S_LEN, 256>>>(x, ln2_g + (size_t)i * D_DIM, ln2_b + (size_t)i * D_DIM, h);

        {
            dim3 grid(FF_DIM / 128, S_LEN / 128);
            gemm_tf32_kernel<1><<<grid, 256>>>(h, f1w, f1b, nullptr, ff, S_LEN, FF_DIM, D_DIM);
        }

        {
            dim3 grid(D_DIM / 128, S_LEN / 128);
            gemm_tf32_kernel<2><<<grid, 256>>>(ff, f2w, f2b, x, x, S_LEN, D_DIM, FF_DIM);
        }
    }
}

// round 5
// speedup vs baseline: 16.0991x; 1.5370x over previous
#include <cuda_runtime.h>
#include <cuda_fp16.h>
#include <math.h>
#include <stdint.h>

#define S_LEN 2048
#define D_DIM 1024
#define H_NUM 16
#define HD_DIM 64
#define FF_DIM 4096
#define DEPTH 2
#define NSEG 4
#define EPS 1e-6f

// ---------------- scratch (device globals; allocation-free) ----------------
__device__ __half g_h  [S_LEN * D_DIM];          // LN output (half)
__device__ float  g_qkv[S_LEN * 3 * D_DIM];      // qkv projection (fp32)
__device__ __half g_ao [S_LEN * D_DIM];          // attention output (half)
__device__ __half g_ff [S_LEN * FF_DIM];         // fc1+gelu output (half)
// half weights
__device__ __half g_wq[DEPTH * D_DIM * 3 * D_DIM];
__device__ __half g_wp[DEPTH * D_DIM * D_DIM];
__device__ __half g_w1[DEPTH * D_DIM * FF_DIM];
__device__ __half g_w2[DEPTH * FF_DIM * D_DIM];

// ---------------- helpers ----------------
__device__ __forceinline__ uint32_t f2tf32(float f) {
    uint32_t r;
    asm("cvt.rna.tf32.f32 %0, %1;" : "=r"(r) : "f"(f));
    return r;
}

__device__ __forceinline__ void mma_tf32(float* d,
                                         uint32_t a0, uint32_t a1, uint32_t a2, uint32_t a3,
                                         uint32_t b0, uint32_t b1) {
    asm volatile(
        "mma.sync.aligned.m16n8k8.row.col.f32.tf32.tf32.f32 "
        "{%0,%1,%2,%3}, {%4,%5,%6,%7}, {%8,%9}, {%0,%1,%2,%3};\n"
        : "+f"(d[0]), "+f"(d[1]), "+f"(d[2]), "+f"(d[3])
        : "r"(a0), "r"(a1), "r"(a2), "r"(a3), "r"(b0), "r"(b1));
}

__device__ __forceinline__ void mma_f16(float* d, const uint32_t* a, const uint32_t* b) {
    asm volatile(
        "mma.sync.aligned.m16n8k16.row.col.f32.f16.f16.f32 "
        "{%0,%1,%2,%3}, {%4,%5,%6,%7}, {%8,%9}, {%0,%1,%2,%3};\n"
        : "+f"(d[0]), "+f"(d[1]), "+f"(d[2]), "+f"(d[3])
        : "r"(a[0]), "r"(a[1]), "r"(a[2]), "r"(a[3]), "r"(b[0]), "r"(b[1]));
}

__device__ __forceinline__ void ldsm_x4(uint32_t* r, const void* p) {
    uint32_t a = (uint32_t)__cvta_generic_to_shared(p);
    asm volatile("ldmatrix.sync.aligned.m8n8.x4.shared.b16 {%0,%1,%2,%3}, [%4];"
                 : "=r"(r[0]), "=r"(r[1]), "=r"(r[2]), "=r"(r[3]) : "r"(a));
}
__device__ __forceinline__ void ldsm_x4_t(uint32_t* r, const void* p) {
    uint32_t a = (uint32_t)__cvta_generic_to_shared(p);
    asm volatile("ldmatrix.sync.aligned.m8n8.x4.trans.shared.b16 {%0,%1,%2,%3}, [%4];"
                 : "=r"(r[0]), "=r"(r[1]), "=r"(r[2]), "=r"(r[3]) : "r"(a));
}

__device__ __forceinline__ void cp16(void* dst, const void* src) {
    uint32_t d = (uint32_t)__cvta_generic_to_shared(dst);
    asm volatile("cp.async.cg.shared.global [%0], [%1], 16;\n" :: "r"(d), "l"(src));
}
__device__ __forceinline__ void cp_commit() {
    asm volatile("cp.async.commit_group;\n");
}

// ---------------- fp32 -> fp16 weight conversion ----------------
__global__ void f2h_kernel(const float* __restrict__ in, __half* __restrict__ out, int n2) {
    int i = blockIdx.x * blockDim.x + threadIdx.x;
    if (i < n2) {
        float2 v = *(const float2*)(in + 2 * i);
        *(__half2*)(out + 2 * i) = __floats2half2_rn(v.x, v.y);
    }
}

// ---------------- LayerNorm: one block per row, half output ----------------
__global__ void ln_kernel(const float* __restrict__ x,
                          const float* __restrict__ g,
                          const float* __restrict__ b,
                          __half* __restrict__ out) {
    const int row = blockIdx.x;
    const int tid = threadIdx.x;                // 256 threads
    const float* xr = x + (size_t)row * D_DIM;
    __shared__ float red[256];

    float s = 0.f;
    for (int i = tid; i < D_DIM; i += 256) s += xr[i];
    red[tid] = s; __syncthreads();
    for (int o = 128; o > 0; o >>= 1) { if (tid < o) red[tid] += red[tid + o]; __syncthreads(); }
    const float mean = red[0] * (1.f / D_DIM);
    __syncthreads();

    float v = 0.f;
    for (int i = tid; i < D_DIM; i += 256) { float d = xr[i] - mean; v += d * d; }
    red[tid] = v; __syncthreads();
    for (int o = 128; o > 0; o >>= 1) { if (tid < o) red[tid] += red[tid + o]; __syncthreads(); }
    const float rstd = rsqrtf(red[0] * (1.f / D_DIM) + EPS);

    for (int i = tid; i < D_DIM; i += 256)
        out[(size_t)row * D_DIM + i] = __float2half((xr[i] - mean) * rstd * g[i] + b[i]);
}

// ------------- FP16 GEMM: 128x128 tile, BK=32, cp.async + ldmatrix ---------
// C[M,N] = A[M,K](half) @ B[K,N](half) + bias (+ epilogue), fp32 accumulate
// EPI: 0 = bias only (float C), 1 = bias + exact GELU (half C), 2 = bias+resid (float C)
template<int EPI, typename CT>
__global__ __launch_bounds__(256)
void gemm_f16_kernel(const __half* __restrict__ A,
                     const __half* __restrict__ B,
                     const float* __restrict__ bias,
                     const float* __restrict__ resid,
                     CT* __restrict__ C,
                     int M, int N, int K) {
    __shared__ __half As[2][128][40];   // stride 80B -> conflict-free ldmatrix
    __shared__ __half Bs[2][32][136];   // stride 272B -> conflict-free ldmatrix

    const int tid  = threadIdx.x;
    const int lane = tid & 31;
    const int wid  = tid >> 5;
    const int warp_m = wid & 1;     // 2 warps over M (64 each)
    const int warp_n = wid >> 1;    // 4 warps over N (32 each)
    const int g = lane >> 2;
    const int t = lane & 3;

    const int bx = blockIdx.x;
    const int by = blockIdx.y;

    const __half* Ag = A + (size_t)by * 128 * K;
    const __half* Bg = B + (size_t)bx * 128;

    float acc[4][4][4];
    #pragma unroll
    for (int mi = 0; mi < 4; mi++)
        #pragma unroll
        for (int ni = 0; ni < 4; ni++)
            #pragma unroll
            for (int e = 0; e < 4; e++) acc[mi][ni][e] = 0.f;

    const int NIT = K >> 5;

    // prefetch stage 0
    {
        #pragma unroll
        for (int i = 0; i < 2; i++) {
            int id = tid + 256 * i;
            int r = id >> 2, c = (id & 3) * 8;
            cp16(&As[0][r][c], Ag + (size_t)r * K + c);
        }
        #pragma unroll
        for (int i = 0; i < 2; i++) {
            int id = tid + 256 * i;
            int r = id >> 4, c = (id & 15) * 8;
            cp16(&Bs[0][r][c], Bg + (size_t)r * N + c);
        }
        cp_commit();
    }

    const int a_row = lane & 15;          // ldmatrix row within 16
    const int a_chk = (lane >> 4) * 8;    // ldmatrix 16B chunk (halfs)

    #pragma unroll 1
    for (int it = 0; it < NIT; it++) {
        const int buf = it & 1;
        if (it + 1 < NIT) {
            const int k0 = (it + 1) << 5;
            #pragma unroll
            for (int i = 0; i < 2; i++) {
                int id = tid + 256 * i;
                int r = id >> 2, c = (id & 3) * 8;
                cp16(&As[buf ^ 1][r][c], Ag + (size_t)r * K + k0 + c);
            }
            #pragma unroll
            for (int i = 0; i < 2; i++) {
                int id = tid + 256 * i;
                int r = id >> 4, c = (id & 15) * 8;
                cp16(&Bs[buf ^ 1][r][c], Bg + (size_t)(k0 + r) * N + c);
            }
            cp_commit();
            asm volatile("cp.async.wait_group 1;\n");
        } else {
            asm volatile("cp.async.wait_group 0;\n");
        }
        __syncthreads();

        #pragma unroll
        for (int ks = 0; ks < 2; ks++) {
            uint32_t af[4][4], bf[4][2];
            #pragma unroll
            for (int mi = 0; mi < 4; mi++) {
                int row = warp_m * 64 + mi * 16 + a_row;
                ldsm_x4(af[mi], &As[buf][row][ks * 16 + a_chk]);
            }
            #pragma unroll
            for (int p = 0; p < 2; p++) {
                uint32_t r[4];
                int krow = ks * 16 + a_row;
                int ncol = warp_n * 32 + p * 16 + a_chk;
                ldsm_x4_t(r, &Bs[buf][krow][ncol]);
                bf[p * 2][0] = r[0]; bf[p * 2][1] = r[1];
                bf[p * 2 + 1][0] = r[2]; bf[p * 2 + 1][1] = r[3];
            }
            #pragma unroll
            for (int mi = 0; mi < 4; mi++)
                #pragma unroll
                for (int ni = 0; ni < 4; ni++)
                    mma_f16(acc[mi][ni], af[mi], bf[ni]);
        }
        __syncthreads();
    }

    // epilogue: ni covers n-offset warp_n*32 + (ni>>1)*16 + (ni&1)*8
    #pragma unroll
    for (int mi = 0; mi < 4; mi++) {
        const int row0 = by * 128 + warp_m * 64 + mi * 16 + g;
        #pragma unroll
        for (int ni = 0; ni < 4; ni++) {
            const int col = bx * 128 + warp_n * 32 + (ni >> 1) * 16 + (ni & 1) * 8 + 2 * t;
            #pragma unroll
            for (int half_ = 0; half_ < 2; half_++) {
                const int r = row0 + half_ * 8;
                #pragma unroll
                for (int e = 0; e < 2; e++) {
                    float v = acc[mi][ni][half_ * 2 + e] + bias[col + e];
                    if (EPI == 1) {
                        v = 0.5f * v * (1.f + erff(v * 0.70710678118654752f));
                    } else if (EPI == 2) {
                        v += resid[(size_t)r * N + col + e];
                    }
                    if (sizeof(CT) == 2) {
                        ((__half*)C)[(size_t)r * N + col + e] = __float2half(v);
                    } else {
                        ((float*)C)[(size_t)r * N + col + e] = v;
                    }
                }
            }
        }
    }
}

// ---------------- RoPE on q and k slices of qkv (fp32) ----------------
__global__ void rope_kernel(float* __restrict__ qkv,
                            const float* __restrict__ cosp,
                            const float* __restrict__ sinp) {
    int idx = blockIdx.x * blockDim.x + threadIdx.x;  // S*H*32
    if (idx >= S_LEN * H_NUM * 32) return;
    const int d = idx & 31;
    const int h = (idx >> 5) & (H_NUM - 1);
    const int s = idx >> (5 + 4);

    const float c1 = cosp[s * 64 + d];
    const float c2 = cosp[s * 64 + d + 32];
    const float s1 = sinp[s * 64 + d];
    const float s2 = sinp[s * 64 + d + 32];

    size_t base = (size_t)s * (3 * D_DIM) + h * HD_DIM + d;
    float q1 = qkv[base], q2 = qkv[base + 32];
    qkv[base]      = q1 * c1 - q2 * s1;
    qkv[base + 32] = q2 * c2 + q1 * s2;
    float k1 = qkv[base + D_DIM], k2 = qkv[base + D_DIM + 32];
    qkv[base + D_DIM]      = k1 * c1 - k2 * s1;
    qkv[base + D_DIM + 32] = k2 * c2 + k1 * s2;
}

// ---------- tensor-core flash attention (tf32), half output ---------
__global__ __launch_bounds__(256)
void attn_kernel(const float* __restrict__ qkv,
                 const int* __restrict__ cu,
                 __half* __restrict__ ao) {
    const int h  = blockIdx.y;
    const int s0 = blockIdx.x * 128;
    const int tid  = threadIdx.x;
    const int lane = tid & 31;
    const int wid  = tid >> 5;
    const int g = lane >> 2;
    const int t = lane & 3;

    __shared__ float Ks[32][68];
    __shared__ float Vs[32][72];
    __shared__ float Ps[128][36];

    int start = 0, len = S_LEN;
    #pragma unroll
    for (int i = 0; i < NSEG; i++) {
        int a = cu[i], b = cu[i + 1];
        if (s0 >= a && s0 < b) { start = a; len = b - a; }
    }

    uint32_t qf[8][4];
    {
        const float* q0 = qkv + (size_t)(s0 + wid * 16 + g) * (3 * D_DIM) + h * HD_DIM;
        const float* q8 = q0 + 8 * (3 * D_DIM);
        #pragma unroll
        for (int ks = 0; ks < 8; ks++) {
            qf[ks][0] = f2tf32(q0[8 * ks + t]     * 0.125f);
            qf[ks][1] = f2tf32(q8[8 * ks + t]     * 0.125f);
            qf[ks][2] = f2tf32(q0[8 * ks + t + 4] * 0.125f);
            qf[ks][3] = f2tf32(q8[8 * ks + t + 4] * 0.125f);
        }
    }

    float m0 = -3.4e38f, m1 = -3.4e38f, l0 = 0.f, l1 = 0.f;
    float out[8][4];
    #pragma unroll
    for (int n = 0; n < 8; n++)
        #pragma unroll
        for (int e = 0; e < 4; e++) out[n][e] = 0.f;

    const int pr = wid * 16;
    const int nch = len >> 5;
    for (int c = 0; c < nch; c++) {
        const int kb = start + c * 32;
        #pragma unroll
        for (int i = 0; i < 2; i++) {
            int id = tid + 256 * i;
            int r = id >> 4, c4 = (id & 15) * 4;
            const float* base = qkv + (size_t)(kb + r) * (3 * D_DIM) + h * HD_DIM + c4;
            float4 kv = *(const float4*)(base + D_DIM);
            float4 vv = *(const float4*)(base + 2 * D_DIM);
            Ks[r][c4 + 0] = __uint_as_float(f2tf32(kv.x));
            Ks[r][c4 + 1] = __uint_as_float(f2tf32(kv.y));
            Ks[r][c4 + 2] = __uint_as_float(f2tf32(kv.z));
            Ks[r][c4 + 3] = __uint_as_float(f2tf32(kv.w));
            Vs[r][c4 + 0] = __uint_as_float(f2tf32(vv.x));
            Vs[r][c4 + 1] = __uint_as_float(f2tf32(vv.y));
            Vs[r][c4 + 2] = __uint_as_float(f2tf32(vv.z));
            Vs[r][c4 + 3] = __uint_as_float(f2tf32(vv.w));
        }
        __syncthreads();

        float sacc[4][4];
        #pragma unroll
        for (int j = 0; j < 4; j++)
            #pragma unroll
            for (int e = 0; e < 4; e++) sacc[j][e] = 0.f;
        #pragma unroll
        for (int ks = 0; ks < 8; ks++) {
            #pragma unroll
            for (int j = 0; j < 4; j++) {
                uint32_t b0 = __float_as_uint(Ks[8 * j + g][8 * ks + t]);
                uint32_t b1 = __float_as_uint(Ks[8 * j + g][8 * ks + t + 4]);
                mma_tf32(sacc[j], qf[ks][0], qf[ks][1], qf[ks][2], qf[ks][3], b0, b1);
            }
        }

        float ml0 = -3.4e38f, ml1 = -3.4e38f;
        #pragma unroll
        for (int j = 0; j < 4; j++) {
            ml0 = fmaxf(ml0, fmaxf(sacc[j][0], sacc[j][1]));
            ml1 = fmaxf(ml1, fmaxf(sacc[j][2], sacc[j][3]));
        }
        ml0 = fmaxf(ml0, __shfl_xor_sync(0xffffffffu, ml0, 1));
        ml0 = fmaxf(ml0, __shfl_xor_sync(0xffffffffu, ml0, 2));
        ml1 = fmaxf(ml1, __shfl_xor_sync(0xffffffffu, ml1, 1));
        ml1 = fmaxf(ml1, __shfl_xor_sync(0xffffffffu, ml1, 2));
        const float mn0 = fmaxf(m0, ml0);
        const float mn1 = fmaxf(m1, ml1);
        const float f0 = __expf(m0 - mn0);
        const float f1 = __expf(m1 - mn1);

        float ll0 = 0.f, ll1 = 0.f;
        #pragma unroll
        for (int j = 0; j < 4; j++) {
            float p0 = __expf(sacc[j][0] - mn0);
            float p1 = __expf(sacc[j][1] - mn0);
            float p2 = __expf(sacc[j][2] - mn1);
            float p3 = __expf(sacc[j][3] - mn1);
            ll0 += p0 + p1; ll1 += p2 + p3;
            Ps[pr + g    ][8 * j + 2 * t]     = __uint_as_float(f2tf32(p0));
            Ps[pr + g    ][8 * j + 2 * t + 1] = __uint_as_float(f2tf32(p1));
            Ps[pr + g + 8][8 * j + 2 * t]     = __uint_as_float(f2tf32(p2));
            Ps[pr + g + 8][8 * j + 2 * t + 1] = __uint_as_float(f2tf32(p3));
        }
        ll0 += __shfl_xor_sync(0xffffffffu, ll0, 1);
        ll0 += __shfl_xor_sync(0xffffffffu, ll0, 2);
        ll1 += __shfl_xor_sync(0xffffffffu, ll1, 1);
        ll1 += __shfl_xor_sync(0xffffffffu, ll1, 2);
        l0 = l0 * f0 + ll0;
        l1 = l1 * f1 + ll1;
        m0 = mn0; m1 = mn1;
        #pragma unroll
        for (int n = 0; n < 8; n++) {
            out[n][0] *= f0; out[n][1] *= f0;
            out[n][2] *= f1; out[n][3] *= f1;
        }
        __syncwarp();

        #pragma unroll
        for (int ks = 0; ks < 4; ks++) {
            uint32_t a0 = __float_as_uint(Ps[pr + g    ][8 * ks + t]);
            uint32_t a1 = __float_as_uint(Ps[pr + g + 8][8 * ks + t]);
            uint32_t a2 = __float_as_uint(Ps[pr + g    ][8 * ks + t + 4]);
            uint32_t a3 = __float_as_uint(Ps[pr + g + 8][8 * ks + t + 4]);
            #pragma unroll
            for (int n = 0; n < 8; n++) {
                uint32_t b0 = __float_as_uint(Vs[8 * ks + t    ][8 * n + g]);
                uint32_t b1 = __float_as_uint(Vs[8 * ks + t + 4][8 * n + g]);
                mma_tf32(out[n], a0, a1, a2, a3, b0, b1);
            }
        }
        __syncthreads();
    }

    const float i0 = 1.f / l0;
    const float i1 = 1.f / l1;
    __half* o0 = ao + (size_t)(s0 + pr + g) * D_DIM + h * HD_DIM;
    __half* o8 = o0 + 8 * D_DIM;
    #pragma unroll
    for (int n = 0; n < 8; n++) {
        *(__half2*)(o0 + 8 * n + 2 * t) = __floats2half2_rn(out[n][0] * i0, out[n][1] * i0);
        *(__half2*)(o8 + 8 * n + 2 * t) = __floats2half2_rn(out[n][2] * i1, out[n][3] * i1);
    }
}

// ---------------- driver ----------------
extern "C" void kernel_launch(void* const* d_in, const int* in_sizes, int n_in,
                              void* d_out, int out_size) {
    const float* hidden = (const float*)d_in[0];
    const int*   cu     = (const int*)d_in[1];
    const float* cosp   = (const float*)d_in[2];
    const float* sinp   = (const float*)d_in[3];
    const float* ln1_g  = (const float*)d_in[4];
    const float* ln1_b  = (const float*)d_in[5];
    const float* qkv_w  = (const float*)d_in[6];
    const float* qkv_b  = (const float*)d_in[7];
    const float* proj_w = (const float*)d_in[8];
    const float* proj_b = (const float*)d_in[9];
    const float* ln2_g  = (const float*)d_in[10];
    const float* ln2_b  = (const float*)d_in[11];
    const float* fc1_w  = (const float*)d_in[12];
    const float* fc1_b  = (const float*)d_in[13];
    const float* fc2_w  = (const float*)d_in[14];
    const float* fc2_b  = (const float*)d_in[15];

    float* x = (float*)d_out;

    __half *h, *ao, *ff, *wq, *wp, *w1, *w2;
    float *qkv;
    cudaGetSymbolAddress((void**)&h,   g_h);
    cudaGetSymbolAddress((void**)&qkv, g_qkv);
    cudaGetSymbolAddress((void**)&ao,  g_ao);
    cudaGetSymbolAddress((void**)&ff,  g_ff);
    cudaGetSymbolAddress((void**)&wq,  g_wq);
    cudaGetSymbolAddress((void**)&wp,  g_wp);
    cudaGetSymbolAddress((void**)&w1,  g_w1);
    cudaGetSymbolAddress((void**)&w2,  g_w2);

    // weight conversions (fp32 -> fp16), once per launch
    {
        int n2;
        n2 = DEPTH * D_DIM * 3 * D_DIM / 2;
        f2h_kernel<<<(n2 + 255) / 256, 256>>>(qkv_w, wq, n2);
        n2 = DEPTH * D_DIM * D_DIM / 2;
        f2h_kernel<<<(n2 + 255) / 256, 256>>>(proj_w, wp, n2);
        n2 = DEPTH * D_DIM * FF_DIM / 2;
        f2h_kernel<<<(n2 + 255) / 256, 256>>>(fc1_w, w1, n2);
        n2 = DEPTH * FF_DIM * D_DIM / 2;
        f2h_kernel<<<(n2 + 255) / 256, 256>>>(fc2_w, w2, n2);
    }

    cudaMemcpyAsync(x, hidden, (size_t)S_LEN * D_DIM * sizeof(float),
                    cudaMemcpyDeviceToDevice);

    for (int i = 0; i < DEPTH; i++) {
        const __half* wqi = wq + (size_t)i * D_DIM * 3 * D_DIM;
        const float*  qb  = qkv_b  + (size_t)i * 3 * D_DIM;
        const __half* wpi = wp + (size_t)i * D_DIM * D_DIM;
        const float*  pb  = proj_b + (size_t)i * D_DIM;
        const __half* w1i = w1 + (size_t)i * D_DIM * FF_DIM;
        const float*  f1b = fc1_b  + (size_t)i * FF_DIM;
        const __half* w2i = w2 + (size_t)i * FF_DIM * D_DIM;
        const float*  f2b = fc2_b  + (size_t)i * D_DIM;

        ln_kernel<<<S_LEN, 256>>>(x, ln1_g + (size_t)i * D_DIM, ln1_b + (size_t)i * D_DIM, h);

        {   // qkv = h @ qkv_w + qkv_b  (fp32 out)
            dim3 grid(3 * D_DIM / 128, S_LEN / 128);
            gemm_f16_kernel<0, float><<<grid, 256>>>(h, wqi, qb, nullptr, qkv,
                                                     S_LEN, 3 * D_DIM, D_DIM);
        }

        {   // RoPE
            int total = S_LEN * H_NUM * 32;
            rope_kernel<<<(total + 255) / 256, 256>>>(qkv, cosp, sinp);
        }

        {   // attention -> half ao
            dim3 grid(S_LEN / 128, H_NUM);
            attn_kernel<<<grid, 256>>>(qkv, cu, ao);
        }

        {   // x += ao @ proj_w + proj_b  (fp32 out)
            dim3 grid(D_DIM / 128, S_LEN / 128);
            gemm_f16_kernel<2, float><<<grid, 256>>>(ao, wpi, pb, x, x,
                                                     S_LEN, D_DIM, D_DIM);
        }

        ln_kernel<<<S_LEN, 256>>>(x, ln2_g + (size_t)i * D_DIM, ln2_b + (size_t)i * D_DIM, h);

        {   // ff = gelu(h @ fc1_w + fc1_b)  (half out)
            dim3 grid(FF_DIM / 128, S_LEN / 128);
            gemm_f16_kernel<1, __half><<<grid, 256>>>(h, w1i, f1b, nullptr, ff,
                                                      S_LEN, FF_DIM, D_DIM);
        }

        {   // x += ff @ fc2_w + fc2_b  (fp32 out)
            dim3 grid(D_DIM / 128, S_LEN / 128);
            gemm_f16_kernel<2, float><<<grid, 256>>>(ff, w2i, f2b, x, x,
                                                     S_LEN, D_DIM, FF_DIM);
        }
    }
}

// round 6
// speedup vs baseline: 16.1026x; 1.0002x over previous
#include <cuda_runtime.h>
#include <cuda_fp16.h>
#include <math.h>
#include <stdint.h>

#define S_LEN 2048
#define D_DIM 1024
#define H_NUM 16
#define HD_DIM 64
#define FF_DIM 4096
#define DEPTH 2
#define NSEG 4
#define EPS 1e-6f

// ---------------- scratch (device globals; allocation-free) ----------------
__device__ __half g_h  [S_LEN * D_DIM];          // LN output (half)
__device__ float  g_qkv[S_LEN * 3 * D_DIM];      // qkv projection (fp32)
__device__ __half g_ao [S_LEN * D_DIM];          // attention output (half)
__device__ __half g_ff [S_LEN * FF_DIM];         // fc1+gelu output (half)
// half weights
__device__ __half g_wq[DEPTH * D_DIM * 3 * D_DIM];
__device__ __half g_wp[DEPTH * D_DIM * D_DIM];
__device__ __half g_w1[DEPTH * D_DIM * FF_DIM];
__device__ __half g_w2[DEPTH * FF_DIM * D_DIM];

// ---------------- helpers ----------------
__device__ __forceinline__ uint32_t f2tf32(float f) {
    uint32_t r;
    asm("cvt.rna.tf32.f32 %0, %1;" : "=r"(r) : "f"(f));
    return r;
}

__device__ __forceinline__ void mma_tf32(float* d,
                                         uint32_t a0, uint32_t a1, uint32_t a2, uint32_t a3,
                                         uint32_t b0, uint32_t b1) {
    asm volatile(
        "mma.sync.aligned.m16n8k8.row.col.f32.tf32.tf32.f32 "
        "{%0,%1,%2,%3}, {%4,%5,%6,%7}, {%8,%9}, {%0,%1,%2,%3};\n"
        : "+f"(d[0]), "+f"(d[1]), "+f"(d[2]), "+f"(d[3])
        : "r"(a0), "r"(a1), "r"(a2), "r"(a3), "r"(b0), "r"(b1));
}

__device__ __forceinline__ void mma_f16(float* d, const uint32_t* a, const uint32_t* b) {
    asm volatile(
        "mma.sync.aligned.m16n8k16.row.col.f32.f16.f16.f32 "
        "{%0,%1,%2,%3}, {%4,%5,%6,%7}, {%8,%9}, {%0,%1,%2,%3};\n"
        : "+f"(d[0]), "+f"(d[1]), "+f"(d[2]), "+f"(d[3])
        : "r"(a[0]), "r"(a[1]), "r"(a[2]), "r"(a[3]), "r"(b[0]), "r"(b[1]));
}

__device__ __forceinline__ void ldsm_x4(uint32_t* r, const void* p) {
    uint32_t a = (uint32_t)__cvta_generic_to_shared(p);
    asm volatile("ldmatrix.sync.aligned.m8n8.x4.shared.b16 {%0,%1,%2,%3}, [%4];"
                 : "=r"(r[0]), "=r"(r[1]), "=r"(r[2]), "=r"(r[3]) : "r"(a));
}
__device__ __forceinline__ void ldsm_x4_t(uint32_t* r, const void* p) {
    uint32_t a = (uint32_t)__cvta_generic_to_shared(p);
    asm volatile("ldmatrix.sync.aligned.m8n8.x4.trans.shared.b16 {%0,%1,%2,%3}, [%4];"
                 : "=r"(r[0]), "=r"(r[1]), "=r"(r[2]), "=r"(r[3]) : "r"(a));
}

__device__ __forceinline__ void cp16(void* dst, const void* src) {
    uint32_t d = (uint32_t)__cvta_generic_to_shared(dst);
    asm volatile("cp.async.cg.shared.global [%0], [%1], 16;\n" :: "r"(d), "l"(src));
}
__device__ __forceinline__ void cp_commit() {
    asm volatile("cp.async.commit_group;\n");
}

// ---------------- fp32 -> fp16 weight conversion ----------------
__global__ void f2h_kernel(const float* __restrict__ in, __half* __restrict__ out, int n2) {
    int i = blockIdx.x * blockDim.x + threadIdx.x;
    if (i < n2) {
        float2 v = *(const float2*)(in + 2 * i);
        *(__half2*)(out + 2 * i) = __floats2half2_rn(v.x, v.y);
    }
}

// ---------------- LayerNorm: one block per row, half output ----------------
__global__ void ln_kernel(const float* __restrict__ x,
                          const float* __restrict__ g,
                          const float* __restrict__ b,
                          __half* __restrict__ out) {
    const int row = blockIdx.x;
    const int tid = threadIdx.x;                // 256 threads
    const float* xr = x + (size_t)row * D_DIM;
    __shared__ float red[256];

    float s = 0.f;
    for (int i = tid; i < D_DIM; i += 256) s += xr[i];
    red[tid] = s; __syncthreads();
    for (int o = 128; o > 0; o >>= 1) { if (tid < o) red[tid] += red[tid + o]; __syncthreads(); }
    const float mean = red[0] * (1.f / D_DIM);
    __syncthreads();

    float v = 0.f;
    for (int i = tid; i < D_DIM; i += 256) { float d = xr[i] - mean; v += d * d; }
    red[tid] = v; __syncthreads();
    for (int o = 128; o > 0; o >>= 1) { if (tid < o) red[tid] += red[tid + o]; __syncthreads(); }
    const float rstd = rsqrtf(red[0] * (1.f / D_DIM) + EPS);

    for (int i = tid; i < D_DIM; i += 256)
        out[(size_t)row * D_DIM + i] = __float2half((xr[i] - mean) * rstd * g[i] + b[i]);
}

// ------------- FP16 GEMM: 128x128 tile, BK=32, cp.async + ldmatrix ---------
// C[M,N] = A[M,K](half) @ B[K,N](half) + bias (+ epilogue), fp32 accumulate
// EPI: 0 = bias only (float C), 1 = bias + exact GELU (half C), 2 = bias+resid (float C)
template<int EPI, typename CT>
__global__ __launch_bounds__(256)
void gemm_f16_kernel(const __half* __restrict__ A,
                     const __half* __restrict__ B,
                     const float* __restrict__ bias,
                     const float* __restrict__ resid,
                     CT* __restrict__ C,
                     int M, int N, int K) {
    __shared__ __half As[2][128][40];   // stride 80B -> conflict-free ldmatrix
    __shared__ __half Bs[2][32][136];   // stride 272B -> conflict-free ldmatrix

    const int tid  = threadIdx.x;
    const int lane = tid & 31;
    const int wid  = tid >> 5;
    const int warp_m = wid & 1;     // 2 warps over M (64 each)
    const int warp_n = wid >> 1;    // 4 warps over N (32 each)
    const int g = lane >> 2;
    const int t = lane & 3;

    const int bx = blockIdx.x;
    const int by = blockIdx.y;

    const __half* Ag = A + (size_t)by * 128 * K;
    const __half* Bg = B + (size_t)bx * 128;

    float acc[4][4][4];
    #pragma unroll
    for (int mi = 0; mi < 4; mi++)
        #pragma unroll
        for (int ni = 0; ni < 4; ni++)
            #pragma unroll
            for (int e = 0; e < 4; e++) acc[mi][ni][e] = 0.f;

    const int NIT = K >> 5;

    // prefetch stage 0
    {
        #pragma unroll
        for (int i = 0; i < 2; i++) {
            int id = tid + 256 * i;
            int r = id >> 2, c = (id & 3) * 8;
            cp16(&As[0][r][c], Ag + (size_t)r * K + c);
        }
        #pragma unroll
        for (int i = 0; i < 2; i++) {
            int id = tid + 256 * i;
            int r = id >> 4, c = (id & 15) * 8;
            cp16(&Bs[0][r][c], Bg + (size_t)r * N + c);
        }
        cp_commit();
    }

    const int a_row = lane & 15;          // ldmatrix row within 16
    const int a_chk = (lane >> 4) * 8;    // ldmatrix 16B chunk (halfs)

    #pragma unroll 1
    for (int it = 0; it < NIT; it++) {
        const int buf = it & 1;
        if (it + 1 < NIT) {
            const int k0 = (it + 1) << 5;
            #pragma unroll
            for (int i = 0; i < 2; i++) {
                int id = tid + 256 * i;
                int r = id >> 2, c = (id & 3) * 8;
                cp16(&As[buf ^ 1][r][c], Ag + (size_t)r * K + k0 + c);
            }
            #pragma unroll
            for (int i = 0; i < 2; i++) {
                int id = tid + 256 * i;
                int r = id >> 4, c = (id & 15) * 8;
                cp16(&Bs[buf ^ 1][r][c], Bg + (size_t)(k0 + r) * N + c);
            }
            cp_commit();
            asm volatile("cp.async.wait_group 1;\n");
        } else {
            asm volatile("cp.async.wait_group 0;\n");
        }
        __syncthreads();

        #pragma unroll
        for (int ks = 0; ks < 2; ks++) {
            uint32_t af[4][4], bf[4][2];
            #pragma unroll
            for (int mi = 0; mi < 4; mi++) {
                int row = warp_m * 64 + mi * 16 + a_row;
                ldsm_x4(af[mi], &As[buf][row][ks * 16 + a_chk]);
            }
            #pragma unroll
            for (int p = 0; p < 2; p++) {
                uint32_t r[4];
                int krow = ks * 16 + a_row;
                int ncol = warp_n * 32 + p * 16 + a_chk;
                ldsm_x4_t(r, &Bs[buf][krow][ncol]);
                bf[p * 2][0] = r[0]; bf[p * 2][1] = r[1];
                bf[p * 2 + 1][0] = r[2]; bf[p * 2 + 1][1] = r[3];
            }
            #pragma unroll
            for (int mi = 0; mi < 4; mi++)
                #pragma unroll
                for (int ni = 0; ni < 4; ni++)
                    mma_f16(acc[mi][ni], af[mi], bf[ni]);
        }
        __syncthreads();
    }

    // epilogue: ni covers n-offset warp_n*32 + (ni>>1)*16 + (ni&1)*8
    #pragma unroll
    for (int mi = 0; mi < 4; mi++) {
        const int row0 = by * 128 + warp_m * 64 + mi * 16 + g;
        #pragma unroll
        for (int ni = 0; ni < 4; ni++) {
            const int col = bx * 128 + warp_n * 32 + (ni >> 1) * 16 + (ni & 1) * 8 + 2 * t;
            #pragma unroll
            for (int half_ = 0; half_ < 2; half_++) {
                const int r = row0 + half_ * 8;
                #pragma unroll
                for (int e = 0; e < 2; e++) {
                    float v = acc[mi][ni][half_ * 2 + e] + bias[col + e];
                    if (EPI == 1) {
                        v = 0.5f * v * (1.f + erff(v * 0.70710678118654752f));
                    } else if (EPI == 2) {
                        v += resid[(size_t)r * N + col + e];
                    }
                    if (sizeof(CT) == 2) {
                        ((__half*)C)[(size_t)r * N + col + e] = __float2half(v);
                    } else {
                        ((float*)C)[(size_t)r * N + col + e] = v;
                    }
                }
            }
        }
    }
}

// ---------------- RoPE on q and k slices of qkv (fp32) ----------------
__global__ void rope_kernel(float* __restrict__ qkv,
                            const float* __restrict__ cosp,
                            const float* __restrict__ sinp) {
    int idx = blockIdx.x * blockDim.x + threadIdx.x;  // S*H*32
    if (idx >= S_LEN * H_NUM * 32) return;
    const int d = idx & 31;
    const int h = (idx >> 5) & (H_NUM - 1);
    const int s = idx >> (5 + 4);

    const float c1 = cosp[s * 64 + d];
    const float c2 = cosp[s * 64 + d + 32];
    const float s1 = sinp[s * 64 + d];
    const float s2 = sinp[s * 64 + d + 32];

    size_t base = (size_t)s * (3 * D_DIM) + h * HD_DIM + d;
    float q1 = qkv[base], q2 = qkv[base + 32];
    qkv[base]      = q1 * c1 - q2 * s1;
    qkv[base + 32] = q2 * c2 + q1 * s2;
    float k1 = qkv[base + D_DIM], k2 = qkv[base + D_DIM + 32];
    qkv[base + D_DIM]      = k1 * c1 - k2 * s1;
    qkv[base + D_DIM + 32] = k2 * c2 + k1 * s2;
}

// ---------- tensor-core flash attention (tf32), half output ---------
__global__ __launch_bounds__(256)
void attn_kernel(const float* __restrict__ qkv,
                 const int* __restrict__ cu,
                 __half* __restrict__ ao) {
    const int h  = blockIdx.y;
    const int s0 = blockIdx.x * 128;
    const int tid  = threadIdx.x;
    const int lane = tid & 31;
    const int wid  = tid >> 5;
    const int g = lane >> 2;
    const int t = lane & 3;

    __shared__ float Ks[32][68];
    __shared__ float Vs[32][72];
    __shared__ float Ps[128][36];

    int start = 0, len = S_LEN;
    #pragma unroll
    for (int i = 0; i < NSEG; i++) {
        int a = cu[i], b = cu[i + 1];
        if (s0 >= a && s0 < b) { start = a; len = b - a; }
    }

    uint32_t qf[8][4];
    {
        const float* q0 = qkv + (size_t)(s0 + wid * 16 + g) * (3 * D_DIM) + h * HD_DIM;
        const float* q8 = q0 + 8 * (3 * D_DIM);
        #pragma unroll
        for (int ks = 0; ks < 8; ks++) {
            qf[ks][0] = f2tf32(q0[8 * ks + t]     * 0.125f);
            qf[ks][1] = f2tf32(q8[8 * ks + t]     * 0.125f);
            qf[ks][2] = f2tf32(q0[8 * ks + t + 4] * 0.125f);
            qf[ks][3] = f2tf32(q8[8 * ks + t + 4] * 0.125f);
        }
    }

    float m0 = -3.4e38f, m1 = -3.4e38f, l0 = 0.f, l1 = 0.f;
    float out[8][4];
    #pragma unroll
    for (int n = 0; n < 8; n++)
        #pragma unroll
        for (int e = 0; e < 4; e++) out[n][e] = 0.f;

    const int pr = wid * 16;
    const int nch = len >> 5;
    for (int c = 0; c < nch; c++) {
        const int kb = start + c * 32;
        #pragma unroll
        for (int i = 0; i < 2; i++) {
            int id = tid + 256 * i;
            int r = id >> 4, c4 = (id & 15) * 4;
            const float* base = qkv + (size_t)(kb + r) * (3 * D_DIM) + h * HD_DIM + c4;
            float4 kv = *(const float4*)(base + D_DIM);
            float4 vv = *(const float4*)(base + 2 * D_DIM);
            Ks[r][c4 + 0] = __uint_as_float(f2tf32(kv.x));
            Ks[r][c4 + 1] = __uint_as_float(f2tf32(kv.y));
            Ks[r][c4 + 2] = __uint_as_float(f2tf32(kv.z));
            Ks[r][c4 + 3] = __uint_as_float(f2tf32(kv.w));
            Vs[r][c4 + 0] = __uint_as_float(f2tf32(vv.x));
            Vs[r][c4 + 1] = __uint_as_float(f2tf32(vv.y));
            Vs[r][c4 + 2] = __uint_as_float(f2tf32(vv.z));
            Vs[r][c4 + 3] = __uint_as_float(f2tf32(vv.w));
        }
        __syncthreads();

        float sacc[4][4];
        #pragma unroll
        for (int j = 0; j < 4; j++)
            #pragma unroll
            for (int e = 0; e < 4; e++) sacc[j][e] = 0.f;
        #pragma unroll
        for (int ks = 0; ks < 8; ks++) {
            #pragma unroll
            for (int j = 0; j < 4; j++) {
                uint32_t b0 = __float_as_uint(Ks[8 * j + g][8 * ks + t]);
                uint32_t b1 = __float_as_uint(Ks[8 * j + g][8 * ks + t + 4]);
                mma_tf32(sacc[j], qf[ks][0], qf[ks][1], qf[ks][2], qf[ks][3], b0, b1);
            }
        }

        float ml0 = -3.4e38f, ml1 = -3.4e38f;
        #pragma unroll
        for (int j = 0; j < 4; j++) {
            ml0 = fmaxf(ml0, fmaxf(sacc[j][0], sacc[j][1]));
            ml1 = fmaxf(ml1, fmaxf(sacc[j][2], sacc[j][3]));
        }
        ml0 = fmaxf(ml0, __shfl_xor_sync(0xffffffffu, ml0, 1));
        ml0 = fmaxf(ml0, __shfl_xor_sync(0xffffffffu, ml0, 2));
        ml1 = fmaxf(ml1, __shfl_xor_sync(0xffffffffu, ml1, 1));
        ml1 = fmaxf(ml1, __shfl_xor_sync(0xffffffffu, ml1, 2));
        const float mn0 = fmaxf(m0, ml0);
        const float mn1 = fmaxf(m1, ml1);
        const float f0 = __expf(m0 - mn0);
        const float f1 = __expf(m1 - mn1);

        float ll0 = 0.f, ll1 = 0.f;
        #pragma unroll
        for (int j = 0; j < 4; j++) {
            float p0 = __expf(sacc[j][0] - mn0);
            float p1 = __expf(sacc[j][1] - mn0);
            float p2 = __expf(sacc[j][2] - mn1);
            float p3 = __expf(sacc[j][3] - mn1);
            ll0 += p0 + p1; ll1 += p2 + p3;
            Ps[pr + g    ][8 * j + 2 * t]     = __uint_as_float(f2tf32(p0));
            Ps[pr + g    ][8 * j + 2 * t + 1] = __uint_as_float(f2tf32(p1));
            Ps[pr + g + 8][8 * j + 2 * t]     = __uint_as_float(f2tf32(p2));
            Ps[pr + g + 8][8 * j + 2 * t + 1] = __uint_as_float(f2tf32(p3));
        }
        ll0 += __shfl_xor_sync(0xffffffffu, ll0, 1);
        ll0 += __shfl_xor_sync(0xffffffffu, ll0, 2);
        ll1 += __shfl_xor_sync(0xffffffffu, ll1, 1);
        ll1 += __shfl_xor_sync(0xffffffffu, ll1, 2);
        l0 = l0 * f0 + ll0;
        l1 = l1 * f1 + ll1;
        m0 = mn0; m1 = mn1;
        #pragma unroll
        for (int n = 0; n < 8; n++) {
            out[n][0] *= f0; out[n][1] *= f0;
            out[n][2] *= f1; out[n][3] *= f1;
        }
        __syncwarp();

        #pragma unroll
        for (int ks = 0; ks < 4; ks++) {
            uint32_t a0 = __float_as_uint(Ps[pr + g    ][8 * ks + t]);
            uint32_t a1 = __float_as_uint(Ps[pr + g + 8][8 * ks + t]);
            uint32_t a2 = __float_as_uint(Ps[pr + g    ][8 * ks + t + 4]);
            uint32_t a3 = __float_as_uint(Ps[pr + g + 8][8 * ks + t + 4]);
            #pragma unroll
            for (int n = 0; n < 8; n++) {
                uint32_t b0 = __float_as_uint(Vs[8 * ks + t    ][8 * n + g]);
                uint32_t b1 = __float_as_uint(Vs[8 * ks + t + 4][8 * n + g]);
                mma_tf32(out[n], a0, a1, a2, a3, b0, b1);
            }
        }
        __syncthreads();
    }

    const float i0 = 1.f / l0;
    const float i1 = 1.f / l1;
    __half* o0 = ao + (size_t)(s0 + pr + g) * D_DIM + h * HD_DIM;
    __half* o8 = o0 + 8 * D_DIM;
    #pragma unroll
    for (int n = 0; n < 8; n++) {
        *(__half2*)(o0 + 8 * n + 2 * t) = __floats2half2_rn(out[n][0] * i0, out[n][1] * i0);
        *(__half2*)(o8 + 8 * n + 2 * t) = __floats2half2_rn(out[n][2] * i1, out[n][3] * i1);
    }
}

// ---------------- driver ----------------
extern "C" void kernel_launch(void* const* d_in, const int* in_sizes, int n_in,
                              void* d_out, int out_size) {
    const float* hidden = (const float*)d_in[0];
    const int*   cu     = (const int*)d_in[1];
    const float* cosp   = (const float*)d_in[2];
    const float* sinp   = (const float*)d_in[3];
    const float* ln1_g  = (const float*)d_in[4];
    const float* ln1_b  = (const float*)d_in[5];
    const float* qkv_w  = (const float*)d_in[6];
    const float* qkv_b  = (const float*)d_in[7];
    const float* proj_w = (const float*)d_in[8];
    const float* proj_b = (const float*)d_in[9];
    const float* ln2_g  = (const float*)d_in[10];
    const float* ln2_b  = (const float*)d_in[11];
    const float* fc1_w  = (const float*)d_in[12];
    const float* fc1_b  = (const float*)d_in[13];
    const float* fc2_w  = (const float*)d_in[14];
    const float* fc2_b  = (const float*)d_in[15];

    float* x = (float*)d_out;

    __half *h, *ao, *ff, *wq, *wp, *w1, *w2;
    float *qkv;
    cudaGetSymbolAddress((void**)&h,   g_h);
    cudaGetSymbolAddress((void**)&qkv, g_qkv);
    cudaGetSymbolAddress((void**)&ao,  g_ao);
    cudaGetSymbolAddress((void**)&ff,  g_ff);
    cudaGetSymbolAddress((void**)&wq,  g_wq);
    cudaGetSymbolAddress((void**)&wp,  g_wp);
    cudaGetSymbolAddress((void**)&w1,  g_w1);
    cudaGetSymbolAddress((void**)&w2,  g_w2);

    // weight conversions (fp32 -> fp16), once per launch
    {
        int n2;
        n2 = DEPTH * D_DIM * 3 * D_DIM / 2;
        f2h_kernel<<<(n2 + 255) / 256, 256>>>(qkv_w, wq, n2);
        n2 = DEPTH * D_DIM * D_DIM / 2;
        f2h_kernel<<<(n2 + 255) / 256, 256>>>(proj_w, wp, n2);
        n2 = DEPTH * D_DIM * FF_DIM / 2;
        f2h_kernel<<<(n2 + 255) / 256, 256>>>(fc1_w, w1, n2);
        n2 = DEPTH * FF_DIM * D_DIM / 2;
        f2h_kernel<<<(n2 + 255) / 256, 256>>>(fc2_w, w2, n2);
    }

    cudaMemcpyAsync(x, hidden, (size_t)S_LEN * D_DIM * sizeof(float),
                    cudaMemcpyDeviceToDevice);

    for (int i = 0; i < DEPTH; i++) {
        const __half* wqi = wq + (size_t)i * D_DIM * 3 * D_DIM;
        const float*  qb  = qkv_b  + (size_t)i * 3 * D_DIM;
        const __half* wpi = wp + (size_t)i * D_DIM * D_DIM;
        const float*  pb  = proj_b + (size_t)i * D_DIM;
        const __half* w1i = w1 + (size_t)i * D_DIM * FF_DIM;
        const float*  f1b = fc1_b  + (size_t)i * FF_DIM;
        const __half* w2i = w2 + (size_t)i * FF_DIM * D_DIM;
        const float*  f2b = fc2_b  + (size_t)i * D_DIM;

        ln_kernel<<<S_LEN, 256>>>(x, ln1_g + (size_t)i * D_DIM, ln1_b + (size_t)i * D_DIM, h);

        {   // qkv = h @ qkv_w + qkv_b  (fp32 out)
            dim3 grid(3 * D_DIM / 128, S_LEN / 128);
            gemm_f16_kernel<0, float><<<grid, 256>>>(h, wqi, qb, nullptr, qkv,
                                                     S_LEN, 3 * D_DIM, D_DIM);
        }

        {   // RoPE
            int total = S_LEN * H_NUM * 32;
            rope_kernel<<<(total + 255) / 256, 256>>>(qkv, cosp, sinp);
        }

        {   // attention -> half ao
            dim3 grid(S_LEN / 128, H_NUM);
            attn_kernel<<<grid, 256>>>(qkv, cu, ao);
        }

        {   // x += ao @ proj_w + proj_b  (fp32 out)
            dim3 grid(D_DIM / 128, S_LEN / 128);
            gemm_f16_kernel<2, float><<<grid, 256>>>(ao, wpi, pb, x, x,
                                                     S_LEN, D_DIM, D_DIM);
        }

        ln_kernel<<<S_LEN, 256>>>(x, ln2_g + (size_t)i * D_DIM, ln2_b + (size_t)i * D_DIM, h);

        {   // ff = gelu(h @ fc1_w + fc1_b)  (half out)
            dim3 grid(FF_DIM / 128, S_LEN / 128);
            gemm_f16_kernel<1, __half><<<grid, 256>>>(h, w1i, f1b, nullptr, ff,
                                                      S_LEN, FF_DIM, D_DIM);
        }

        {   // x += ff @ fc2_w + fc2_b  (fp32 out)
            dim3 grid(D_DIM / 128, S_LEN / 128);
            gemm_f16_kernel<2, float><<<grid, 256>>>(ff, w2i, f2b, x, x,
                                                     S_LEN, D_DIM, FF_DIM);
        }
    }
}